// round 1
// baseline (speedup 1.0000x reference)
#include <cuda_runtime.h>
#include <math.h>
#include <stdint.h>

#define BATCH 64
#define CIN   640
#define P1    784    // 28*28
#define P2    196    // 14*14
#define INNER 512
#define NHEAD 8
#define DHEAD 64

// ---------------- scratch (static device arrays; no allocation) ----------------
__device__ float g_dq [BATCH * CIN * P1];       // dwconv-q + BN   [b][ci][p1]
__device__ float g_dkv[BATCH * CIN * P2];       // dwconv-kv + BN  [b][ci][p2]
__device__ float g_q  [BATCH * INNER * P1];     // q               [b][hd][p1]
__device__ float g_kv [BATCH * 2 * INNER * P2]; // k then v        [b][2hd][p2]
__device__ float g_res[BATCH * DHEAD * P1];     // residual + BN   [b][d][p1]

// ---------------- depthwise 3x3 conv + BN (eval) ----------------
__global__ void dwconv_bn_kernel(const float* __restrict__ x,
                                 const float* __restrict__ w,
                                 const float* __restrict__ bg,
                                 const float* __restrict__ bb,
                                 const float* __restrict__ bm,
                                 const float* __restrict__ bv,
                                 float* __restrict__ y,
                                 int C, int H, int W, int OH, int OW,
                                 int stride, int total) {
    int idx = blockIdx.x * blockDim.x + threadIdx.x;
    if (idx >= total) return;
    int ox = idx % OW;
    int t  = idx / OW;
    int oy = t % OH; t /= OH;
    int c  = t % C;
    int b  = t / C;
    const float* xb = x + ((size_t)(b * C + c)) * H * W;
    const float* wc = w + c * 9;
    int iy0 = oy * stride - 1;
    int ix0 = ox * stride - 1;
    float acc = 0.f;
#pragma unroll
    for (int dy = 0; dy < 3; dy++) {
        int iy = iy0 + dy;
        if (iy < 0 || iy >= H) continue;
#pragma unroll
        for (int dx = 0; dx < 3; dx++) {
            int ix = ix0 + dx;
            if (ix < 0 || ix >= W) continue;
            acc += xb[iy * W + ix] * wc[dy * 3 + dx];
        }
    }
    float inv = bg[c] * rsqrtf(bv[c] + 1e-5f);
    y[idx] = (acc - bm[c]) * inv + bb[c];
}

// ---------------- pointwise conv as batched GEMM: Y[b][co][p] = sum_ci W[co][ci]*X[b][ci][p] ----
// optional fused BN on output channel co
__global__ void pw_gemm_kernel(const float* __restrict__ X,
                               const float* __restrict__ W,
                               float* __restrict__ Y,
                               int CO, int CI, int P,
                               const float* __restrict__ bg,
                               const float* __restrict__ bb,
                               const float* __restrict__ bm,
                               const float* __restrict__ bv) {
    __shared__ float Ws[16][64];
    __shared__ float Xs[16][68];
    int b   = blockIdx.z;
    int co0 = blockIdx.y * 64;
    int p0  = blockIdx.x * 64;
    const float* Xb = X + (size_t)b * CI * P;
    float*       Yb = Y + (size_t)b * CO * P;
    int tid = threadIdx.x;
    int tx  = tid & 15;   // p direction
    int ty  = tid >> 4;   // co direction
    float acc[4][4];
#pragma unroll
    for (int i = 0; i < 4; i++)
#pragma unroll
        for (int j = 0; j < 4; j++) acc[i][j] = 0.f;

    for (int k0 = 0; k0 < CI; k0 += 16) {
        // W tile: Ws[k][m] = W[(co0+m)*CI + k0+k]
#pragma unroll
        for (int l = tid; l < 1024; l += 256) {
            int k = l & 15, m = l >> 4;
            int co = co0 + m;
            Ws[k][m] = (co < CO) ? W[(size_t)co * CI + k0 + k] : 0.f;
        }
        // X tile: Xs[k][n] = Xb[(k0+k)*P + p0+n]
#pragma unroll
        for (int l = tid; l < 1024; l += 256) {
            int n = l & 63, k = l >> 6;
            int p = p0 + n;
            Xs[k][n] = (p < P) ? Xb[(size_t)(k0 + k) * P + p] : 0.f;
        }
        __syncthreads();
#pragma unroll
        for (int k = 0; k < 16; k++) {
            float wr[4], xr[4];
#pragma unroll
            for (int i = 0; i < 4; i++) wr[i] = Ws[k][ty * 4 + i];
#pragma unroll
            for (int j = 0; j < 4; j++) xr[j] = Xs[k][tx * 4 + j];
#pragma unroll
            for (int i = 0; i < 4; i++)
#pragma unroll
                for (int j = 0; j < 4; j++) acc[i][j] += wr[i] * xr[j];
        }
        __syncthreads();
    }
#pragma unroll
    for (int i = 0; i < 4; i++) {
        int co = co0 + ty * 4 + i;
        if (co >= CO) continue;
        float scale = 1.f, shift = 0.f;
        if (bg) {
            float inv = bg[co] * rsqrtf(bv[co] + 1e-5f);
            scale = inv;
            shift = bb[co] - bm[co] * inv;
        }
#pragma unroll
        for (int j = 0; j < 4; j++) {
            int p = p0 + tx * 4 + j;
            if (p < P) Yb[(size_t)co * P + p] = acc[i][j] * scale + shift;
        }
    }
}

// ---------------- fused attention + residual + per-head LN + spatial mean ----------------
// one block per (b, h); 8 warps; each warp handles chunks of 4 queries.
#define KSTRIDE 68   // k row stride in smem (float4-aligned, conflict-free)
#define VSTRIDE 66   // v row stride in smem (float2-aligned, conflict-free)

__global__ void attn_kernel(const float* __restrict__ qb,
                            const float* __restrict__ kvb,
                            const float* __restrict__ resb,
                            const float* __restrict__ lng,
                            const float* __restrict__ lnb,
                            float* __restrict__ out) {
    extern __shared__ float sm[];
    float* KS  = sm;                       // 196 * 68
    float* VS  = KS + P2 * KSTRIDE;        // 196 * 66
    float* QS  = VS + P2 * VSTRIDE;        // 8 * 256
    float* PB  = QS + 8 * 256;             // 8 * 784  (196 j * 4 queries interleaved)
    float* ACC = PB + 8 * 784;             // 8 * 64

    int bh = blockIdx.x;
    int b = bh >> 3, h = bh & 7;
    int tid  = threadIdx.x;
    int lane = tid & 31;
    int wid  = tid >> 5;

    const float* kbase = kvb + ((size_t)b * 1024 + h * 64) * P2;
    const float* vbase = kvb + ((size_t)b * 1024 + 512 + h * 64) * P2;
    for (int l = tid; l < P2 * DHEAD; l += 256) {
        int d = l / P2, j = l % P2;
        KS[j * KSTRIDE + d] = kbase[(size_t)d * P2 + j];
        VS[j * VSTRIDE + d] = vbase[(size_t)d * P2 + j];
    }
    __syncthreads();

    const float* qbase = qb + ((size_t)b * 512 + h * 64) * P1;
    const float* rbase = resb + (size_t)b * DHEAD * P1;

    float* qs = QS + wid * 256;   // 4 queries x 64
    float* pb = PB + wid * 784;   // [j][q] interleaved float4

    int d0 = 2 * lane, d1 = 2 * lane + 1;
    float lg0 = lng[h * 64 + d0], lb0 = lnb[h * 64 + d0];
    float lg1 = lng[h * 64 + d1], lb1 = lnb[h * 64 + d1];

    float S0 = 0.f, S1 = 0.f;

    for (int c = wid; c < 196; c += 8) {
        int i0 = c * 4;
        // stage 4 query vectors into smem
#pragma unroll
        for (int q = 0; q < 4; q++) {
            qs[q * 64 + d0] = qbase[(size_t)d0 * P1 + i0 + q];
            qs[q * 64 + d1] = qbase[(size_t)d1 * P1 + i0 + q];
        }
        __syncwarp();

        // ---- phase A: dots + softmax stats ----
        float loc0[7], loc1[7], loc2[7], loc3[7];
        float mx0 = -1e30f, mx1 = -1e30f, mx2 = -1e30f, mx3 = -1e30f;
        const float4* q0p = (const float4*)(qs);
        const float4* q1p = (const float4*)(qs + 64);
        const float4* q2p = (const float4*)(qs + 128);
        const float4* q3p = (const float4*)(qs + 192);
#pragma unroll
        for (int t = 0; t < 7; t++) {
            int j = lane + t * 32;
            float s0 = 0.f, s1 = 0.f, s2 = 0.f, s3 = 0.f;
            if (j < 196) {
                const float4* kr = (const float4*)(KS + j * KSTRIDE);
#pragma unroll
                for (int g4 = 0; g4 < 16; g4++) {
                    float4 kv4 = kr[g4];
                    float4 a;
                    a = q0p[g4]; s0 += a.x*kv4.x + a.y*kv4.y + a.z*kv4.z + a.w*kv4.w;
                    a = q1p[g4]; s1 += a.x*kv4.x + a.y*kv4.y + a.z*kv4.z + a.w*kv4.w;
                    a = q2p[g4]; s2 += a.x*kv4.x + a.y*kv4.y + a.z*kv4.z + a.w*kv4.w;
                    a = q3p[g4]; s3 += a.x*kv4.x + a.y*kv4.y + a.z*kv4.z + a.w*kv4.w;
                }
                s0 *= 0.125f; s1 *= 0.125f; s2 *= 0.125f; s3 *= 0.125f;
                mx0 = fmaxf(mx0, s0); mx1 = fmaxf(mx1, s1);
                mx2 = fmaxf(mx2, s2); mx3 = fmaxf(mx3, s3);
            }
            loc0[t] = s0; loc1[t] = s1; loc2[t] = s2; loc3[t] = s3;
        }
#pragma unroll
        for (int o = 16; o > 0; o >>= 1) {
            mx0 = fmaxf(mx0, __shfl_xor_sync(0xffffffffu, mx0, o));
            mx1 = fmaxf(mx1, __shfl_xor_sync(0xffffffffu, mx1, o));
            mx2 = fmaxf(mx2, __shfl_xor_sync(0xffffffffu, mx2, o));
            mx3 = fmaxf(mx3, __shfl_xor_sync(0xffffffffu, mx3, o));
        }
        float sm0 = 0.f, sm1 = 0.f, sm2 = 0.f, sm3 = 0.f;
#pragma unroll
        for (int t = 0; t < 7; t++) {
            int j = lane + t * 32;
            if (j < 196) {
                float e0 = __expf(loc0[t] - mx0);
                float e1 = __expf(loc1[t] - mx1);
                float e2 = __expf(loc2[t] - mx2);
                float e3 = __expf(loc3[t] - mx3);
                sm0 += e0; sm1 += e1; sm2 += e2; sm3 += e3;
                ((float4*)pb)[j] = make_float4(e0, e1, e2, e3);
            }
        }
#pragma unroll
        for (int o = 16; o > 0; o >>= 1) {
            sm0 += __shfl_xor_sync(0xffffffffu, sm0, o);
            sm1 += __shfl_xor_sync(0xffffffffu, sm1, o);
            sm2 += __shfl_xor_sync(0xffffffffu, sm2, o);
            sm3 += __shfl_xor_sync(0xffffffffu, sm3, o);
        }
        float inv[4];
        inv[0] = 1.f / sm0; inv[1] = 1.f / sm1; inv[2] = 1.f / sm2; inv[3] = 1.f / sm3;
        __syncwarp();

        // ---- phase B: out = attn @ V ----
        float aq[4][2];
#pragma unroll
        for (int q = 0; q < 4; q++) { aq[q][0] = 0.f; aq[q][1] = 0.f; }
        const float4* pbv = (const float4*)pb;
        for (int j = 0; j < 196; j++) {
            float4 pv = pbv[j];
            float2 vv = *((const float2*)(VS + j * VSTRIDE + d0));
            aq[0][0] += pv.x * vv.x; aq[0][1] += pv.x * vv.y;
            aq[1][0] += pv.y * vv.x; aq[1][1] += pv.y * vv.y;
            aq[2][0] += pv.z * vv.x; aq[2][1] += pv.z * vv.y;
            aq[3][0] += pv.w * vv.x; aq[3][1] += pv.w * vv.y;
        }

        // ---- residual + per-head LN + running spatial sum ----
#pragma unroll
        for (int q = 0; q < 4; q++) {
            float o0 = aq[q][0] * inv[q] + rbase[(size_t)d0 * P1 + i0 + q];
            float o1 = aq[q][1] * inv[q] + rbase[(size_t)d1 * P1 + i0 + q];
            float s1v = o0 + o1;
            float s2v = o0 * o0 + o1 * o1;
#pragma unroll
            for (int o = 16; o > 0; o >>= 1) {
                s1v += __shfl_xor_sync(0xffffffffu, s1v, o);
                s2v += __shfl_xor_sync(0xffffffffu, s2v, o);
            }
            float mean = s1v * (1.f / 64.f);
            float var  = s2v * (1.f / 64.f) - mean * mean;
            var = fmaxf(var, 0.f);
            float istd = 1.f / (sqrtf(var) + 1e-5f);
            S0 += (o0 - mean) * istd * lg0 + lb0;
            S1 += (o1 - mean) * istd * lg1 + lb1;
        }
        __syncwarp();
    }

    ACC[wid * 64 + d0] = S0;
    ACC[wid * 64 + d1] = S1;
    __syncthreads();
    if (tid < 64) {
        float s = 0.f;
#pragma unroll
        for (int w = 0; w < 8; w++) s += ACC[w * 64 + tid];
        out[(size_t)bh * 64 + tid] = s * (1.f / 784.f);
    }
}

// ---------------- launch ----------------
extern "C" void kernel_launch(void* const* d_in, const int* in_sizes, int n_in,
                              void* d_out, int out_size) {
    (void)in_sizes; (void)n_in; (void)out_size;
    const float* x      = (const float*)d_in[0];
    const float* w_dwq  = (const float*)d_in[1];
    const float* w_pwq  = (const float*)d_in[2];
    const float* w_dwkv = (const float*)d_in[3];
    const float* w_pwkv = (const float*)d_in[4];
    const float* w_ds   = (const float*)d_in[5];
    const float* ln_g   = (const float*)d_in[6];
    const float* ln_b   = (const float*)d_in[7];
    const float* bnq_g  = (const float*)d_in[8];
    const float* bnq_b  = (const float*)d_in[9];
    const float* bnq_m  = (const float*)d_in[10];
    const float* bnq_v  = (const float*)d_in[11];
    const float* bnkv_g = (const float*)d_in[12];
    const float* bnkv_b = (const float*)d_in[13];
    const float* bnkv_m = (const float*)d_in[14];
    const float* bnkv_v = (const float*)d_in[15];
    const float* bnds_g = (const float*)d_in[16];
    const float* bnds_b = (const float*)d_in[17];
    const float* bnds_m = (const float*)d_in[18];
    const float* bnds_v = (const float*)d_in[19];
    float* out = (float*)d_out;

    float *dq, *dkv, *qb, *kvb, *resb;
    cudaGetSymbolAddress((void**)&dq,   g_dq);
    cudaGetSymbolAddress((void**)&dkv,  g_dkv);
    cudaGetSymbolAddress((void**)&qb,   g_q);
    cudaGetSymbolAddress((void**)&kvb,  g_kv);
    cudaGetSymbolAddress((void**)&resb, g_res);

    // 1) depthwise convs + BN
    int tot1 = BATCH * CIN * P1;
    dwconv_bn_kernel<<<(tot1 + 255) / 256, 256>>>(
        x, w_dwq, bnq_g, bnq_b, bnq_m, bnq_v, dq, CIN, 28, 28, 28, 28, 1, tot1);
    int tot2 = BATCH * CIN * P2;
    dwconv_bn_kernel<<<(tot2 + 255) / 256, 256>>>(
        x, w_dwkv, bnkv_g, bnkv_b, bnkv_m, bnkv_v, dkv, CIN, 28, 28, 14, 14, 2, tot2);

    // 2) pointwise convs as batched GEMMs
    dim3 gq((P1 + 63) / 64, INNER / 64, BATCH);
    pw_gemm_kernel<<<gq, 256>>>(dq, w_pwq, qb, INNER, CIN, P1,
                                nullptr, nullptr, nullptr, nullptr);
    dim3 gkv((P2 + 63) / 64, (2 * INNER) / 64, BATCH);
    pw_gemm_kernel<<<gkv, 256>>>(dkv, w_pwkv, kvb, 2 * INNER, CIN, P2,
                                 nullptr, nullptr, nullptr, nullptr);
    dim3 gr((P1 + 63) / 64, 1, BATCH);
    pw_gemm_kernel<<<gr, 256>>>(x, w_ds, resb, DHEAD, CIN, P1,
                                bnds_g, bnds_b, bnds_m, bnds_v);

    // 3) fused attention + residual + LN + mean
    size_t smem = (size_t)(P2 * KSTRIDE + P2 * VSTRIDE + 8 * 256 + 8 * 784 + 512) * sizeof(float);
    cudaFuncSetAttribute(attn_kernel, cudaFuncAttributeMaxDynamicSharedMemorySize, (int)smem);
    attn_kernel<<<BATCH * NHEAD, 256, smem>>>(qb, kvb, resb, ln_g, ln_b, out);
}

// round 3
// speedup vs baseline: 1.3430x; 1.3430x over previous
#include <cuda_runtime.h>
#include <cuda_bf16.h>
#include <math.h>
#include <stdint.h>

#define BATCH 64
#define CIN   640
#define P1    784    // 28*28
#define P2    196    // 14*14
#define NQ    (BATCH * P1)   // 50176
#define NKV   (BATCH * P2)   // 12544
#define INNER 512
#define NHEAD 8
#define DHEAD 64
#define ASTRIDE 72           // smem row stride in bf16 (64 data + 8 pad) -> 144B = 36 banks, conflict-free

// ---------------- scratch (static device arrays; no allocation) ----------------
__device__ float          g_dq  [CIN * NQ];        // dwconv-q + BN  [c][n]
__device__ float          g_dkv [CIN * NKV];       // dwconv-kv + BN [c][n]
__device__ __nv_bfloat16  g_hiq [NQ * CIN];        // activations hi [n][c]
__device__ __nv_bfloat16  g_loq [NQ * CIN];
__device__ __nv_bfloat16  g_hikv[NKV * CIN];
__device__ __nv_bfloat16  g_lokv[NKV * CIN];
__device__ __nv_bfloat16  g_hix [NQ * CIN];        // raw x transposed hi/lo (for residual)
__device__ __nv_bfloat16  g_lox [NQ * CIN];
__device__ __nv_bfloat16  g_hwq [INNER * CIN];     // weights hi/lo  [co][c]
__device__ __nv_bfloat16  g_lwq [INNER * CIN];
__device__ __nv_bfloat16  g_hwkv[2 * INNER * CIN];
__device__ __nv_bfloat16  g_lwkv[2 * INNER * CIN];
__device__ __nv_bfloat16  g_hwds[128 * CIN];       // padded to 128 rows
__device__ __nv_bfloat16  g_lwds[128 * CIN];
__device__ float          g_q   [NQ * INNER];      // q  [n][hd]
__device__ float          g_kv  [NKV * 2 * INNER]; // kv [n][2hd]
__device__ float          g_res [NQ * DHEAD];      // residual [n][d]

// =================== helpers ===================
__device__ __forceinline__ uint32_t smem_u32(const void* p) {
    uint32_t a;
    asm("{ .reg .u64 t; cvta.to.shared.u64 t, %1; cvt.u32.u64 %0, t; }" : "=r"(a) : "l"(p));
    return a;
}
#define CP_ASYNC16(sa, ga) \
    asm volatile("cp.async.cg.shared.global [%0], [%1], 16;" :: "r"(sa), "l"(ga))
#define CP_COMMIT() asm volatile("cp.async.commit_group;")
#define CP_WAIT(n)  asm volatile("cp.async.wait_group %0;" :: "n"(n))

// ---------------- depthwise 3x3 conv + BN (eval), output [c][b][oy][ox] ----------------
__global__ void dwconv_bn_kernel(const float* __restrict__ x,
                                 const float* __restrict__ w,
                                 const float* __restrict__ bg, const float* __restrict__ bb,
                                 const float* __restrict__ bm, const float* __restrict__ bv,
                                 float* __restrict__ y,
                                 int C, int H, int W, int OH, int OW, int stride, int total) {
    int idx = blockIdx.x * blockDim.x + threadIdx.x;
    if (idx >= total) return;
    int ox = idx % OW;
    int t  = idx / OW;
    int oy = t % OH; t /= OH;
    int b  = t % BATCH;
    int c  = t / BATCH;
    const float* xb = x + ((size_t)(b * C + c)) * H * W;
    const float* wc = w + c * 9;
    int iy0 = oy * stride - 1, ix0 = ox * stride - 1;
    float acc = 0.f;
#pragma unroll
    for (int dy = 0; dy < 3; dy++) {
        int iy = iy0 + dy;
        if (iy < 0 || iy >= H) continue;
#pragma unroll
        for (int dx = 0; dx < 3; dx++) {
            int ix = ix0 + dx;
            if (ix < 0 || ix >= W) continue;
            acc += xb[iy * W + ix] * wc[dy * 3 + dx];
        }
    }
    float inv = bg[c] * rsqrtf(bv[c] + 1e-5f);
    y[idx] = (acc - bm[c]) * inv + bb[c];
}

// ---------------- transpose [K][N] fp32 -> [N][K] bf16 hi/lo split (K,N mult of 32) --------
__global__ void tsplit_kernel(const float* __restrict__ X,
                              __nv_bfloat16* __restrict__ hi, __nv_bfloat16* __restrict__ lo,
                              int K, int N) {
    __shared__ float t[32][33];
    int n0 = blockIdx.x * 32, k0 = blockIdx.y * 32;
    int tx = threadIdx.x, ty = threadIdx.y;   // block (32, 8)
#pragma unroll
    for (int r = 0; r < 4; r++)
        t[ty + r * 8][tx] = X[(size_t)(k0 + ty + r * 8) * N + n0 + tx];
    __syncthreads();
#pragma unroll
    for (int r = 0; r < 4; r++) {
        int nn = ty + r * 8;
        float v  = t[tx][nn];
        __nv_bfloat16 h = __float2bfloat16(v);
        float rem = v - __bfloat162float(h);
        size_t o = (size_t)(n0 + nn) * K + k0 + tx;
        hi[o] = h;
        lo[o] = __float2bfloat16(rem);
    }
}

// ---------------- per-batch transpose of x: [b][C][P1] -> [(b*P1+p)][C] hi/lo ----------------
__global__ void tsplit_x_kernel(const float* __restrict__ X,
                                __nv_bfloat16* __restrict__ hi, __nv_bfloat16* __restrict__ lo) {
    __shared__ float t[32][33];
    int b  = blockIdx.z;
    int p0 = blockIdx.x * 32, c0 = blockIdx.y * 32;
    int tx = threadIdx.x, ty = threadIdx.y;  // (32,8)
#pragma unroll
    for (int r = 0; r < 4; r++) {
        int c = c0 + ty + r * 8;
        int p = p0 + tx;
        t[ty + r * 8][tx] = (p < P1) ? X[((size_t)b * CIN + c) * P1 + p] : 0.f;
    }
    __syncthreads();
#pragma unroll
    for (int r = 0; r < 4; r++) {
        int p = p0 + ty + r * 8;
        int c = c0 + tx;
        if (p < P1) {
            float v = t[tx][ty + r * 8];
            __nv_bfloat16 h = __float2bfloat16(v);
            float rem = v - __bfloat162float(h);
            size_t o = ((size_t)b * P1 + p) * CIN + c;
            hi[o] = h;
            lo[o] = __float2bfloat16(rem);
        }
    }
}

// ---------------- weight fp32 -> bf16 hi/lo split (zero-pad to n_tot) ----------------
__global__ void wsplit_kernel(const float* __restrict__ W,
                              __nv_bfloat16* __restrict__ hi, __nv_bfloat16* __restrict__ lo,
                              int n_src, int n_tot) {
    int i = blockIdx.x * blockDim.x + threadIdx.x;
    if (i >= n_tot) return;
    float v = (i < n_src) ? W[i] : 0.f;
    __nv_bfloat16 h = __float2bfloat16(v);
    hi[i] = h;
    lo[i] = __float2bfloat16(v - __bfloat162float(h));
}

// ---------------- mma.sync bf16 split GEMM ----------------
// D[m][n] = sum over K_cat=1920 of Wseg[m][k]*Xseg[n][k]
// seg0: hiW*hiX, seg1: loW*hiX, seg2: hiW*loX   (each 640 K)
// Y[n][CO] = D (+ optional per-m BN). CTA tile 128x128, 8 warps (2x4), K-stage 64.
__global__ void __launch_bounds__(256)
mma_gemm_kernel(const __nv_bfloat16* __restrict__ hiW, const __nv_bfloat16* __restrict__ loW,
                const __nv_bfloat16* __restrict__ hiX, const __nv_bfloat16* __restrict__ loX,
                float* __restrict__ Y, int CO, int N,
                const float* __restrict__ bg, const float* __restrict__ bb,
                const float* __restrict__ bm, const float* __restrict__ bv) {
    extern __shared__ __nv_bfloat16 smem[];
    __nv_bfloat16* As[2] = { smem,                  smem + 2 * 128 * ASTRIDE };
    __nv_bfloat16* Bs[2] = { smem + 128 * ASTRIDE,  smem + 3 * 128 * ASTRIDE };

    int tid = threadIdx.x, lane = tid & 31, wid = tid >> 5;
    int warp_m = wid >> 2, warp_n = wid & 3;
    int m0 = blockIdx.y * 128, n0 = blockIdx.x * 128;

    int lrow = tid >> 1, lhalf = tid & 1;  // global->smem: 2 threads per row, 32 bf16 each

    float acc[4][4][4];
#pragma unroll
    for (int i = 0; i < 4; i++)
#pragma unroll
        for (int j = 0; j < 4; j++)
#pragma unroll
            for (int k = 0; k < 4; k++) acc[i][j][k] = 0.f;

    // per-lane ldmatrix byte offsets within a tile
    int a_row = warp_m * 64 + ((lane & 7) | (((lane >> 3) & 1) << 3));
    int a_off = a_row * (ASTRIDE * 2) + (lane >> 4) * 16;
    int b_row = warp_n * 32 + (lane & 7);
    int b_off = b_row * (ASTRIDE * 2) + ((lane >> 3) & 1) * 16;

#define LOAD_STAGE(s, buf) do { \
        int _seg = (s) / 10; \
        int _kk  = ((s) % 10) * 64; \
        const __nv_bfloat16* _Ap = (_seg == 1 ? loW : hiW) + (size_t)(m0 + lrow) * CIN + _kk + lhalf * 32; \
        const __nv_bfloat16* _Bp = (_seg == 2 ? loX : hiX) + (size_t)(n0 + lrow) * CIN + _kk + lhalf * 32; \
        uint32_t _sa = smem_u32(As[buf] + lrow * ASTRIDE + lhalf * 32); \
        uint32_t _sb = smem_u32(Bs[buf] + lrow * ASTRIDE + lhalf * 32); \
        CP_ASYNC16(_sa,      _Ap);      CP_ASYNC16(_sb,      _Bp); \
        CP_ASYNC16(_sa + 16, _Ap + 8);  CP_ASYNC16(_sb + 16, _Bp + 8); \
        CP_ASYNC16(_sa + 32, _Ap + 16); CP_ASYNC16(_sb + 32, _Bp + 16); \
        CP_ASYNC16(_sa + 48, _Ap + 24); CP_ASYNC16(_sb + 48, _Bp + 24); \
        CP_COMMIT(); \
    } while (0)

    LOAD_STAGE(0, 0);

    for (int s = 0; s < 30; s++) {
        int buf = s & 1;
        if (s + 1 < 30) {
            LOAD_STAGE(s + 1, buf ^ 1);
            CP_WAIT(1);
        } else {
            CP_WAIT(0);
        }
        __syncthreads();

        uint32_t abase = smem_u32(As[buf]) + a_off;
        uint32_t bbase = smem_u32(Bs[buf]) + b_off;
#pragma unroll
        for (int ks = 0; ks < 4; ks++) {
            uint32_t a[4][4], bfr[4][2];
#pragma unroll
            for (int mt = 0; mt < 4; mt++) {
                uint32_t addr = abase + mt * 16 * (ASTRIDE * 2) + ks * 32;
                asm volatile("ldmatrix.sync.aligned.m8n8.x4.shared.b16 {%0,%1,%2,%3}, [%4];"
                             : "=r"(a[mt][0]), "=r"(a[mt][1]), "=r"(a[mt][2]), "=r"(a[mt][3])
                             : "r"(addr));
            }
#pragma unroll
            for (int nt = 0; nt < 4; nt++) {
                uint32_t addr = bbase + nt * 8 * (ASTRIDE * 2) + ks * 32;
                asm volatile("ldmatrix.sync.aligned.m8n8.x2.shared.b16 {%0,%1}, [%2];"
                             : "=r"(bfr[nt][0]), "=r"(bfr[nt][1])
                             : "r"(addr));
            }
#pragma unroll
            for (int mt = 0; mt < 4; mt++)
#pragma unroll
                for (int nt = 0; nt < 4; nt++) {
                    asm volatile(
                        "mma.sync.aligned.m16n8k16.row.col.f32.bf16.bf16.f32 "
                        "{%0,%1,%2,%3}, {%4,%5,%6,%7}, {%8,%9}, {%0,%1,%2,%3};"
                        : "+f"(acc[mt][nt][0]), "+f"(acc[mt][nt][1]),
                          "+f"(acc[mt][nt][2]), "+f"(acc[mt][nt][3])
                        : "r"(a[mt][0]), "r"(a[mt][1]), "r"(a[mt][2]), "r"(a[mt][3]),
                          "r"(bfr[nt][0]), "r"(bfr[nt][1]));
                }
        }
        __syncthreads();
    }

    // epilogue: Y[n][CO] (+ optional BN on m), guard m<CO
    int g = lane >> 2, t4 = lane & 3;
#pragma unroll
    for (int mt = 0; mt < 4; mt++) {
        int mA = m0 + warp_m * 64 + mt * 16 + g;
        int mB = mA + 8;
        bool wA = mA < CO, wB = mB < CO;
        float sA = 1.f, hA = 0.f, sB = 1.f, hB = 0.f;
        if (bg) {
            if (wA) { float iv = bg[mA] * rsqrtf(bv[mA] + 1e-5f); sA = iv; hA = bb[mA] - bm[mA] * iv; }
            if (wB) { float iv = bg[mB] * rsqrtf(bv[mB] + 1e-5f); sB = iv; hB = bb[mB] - bm[mB] * iv; }
        }
#pragma unroll
        for (int nt = 0; nt < 4; nt++) {
            size_t n = n0 + warp_n * 32 + nt * 8 + 2 * t4;
            if (wA) {
                Y[n * CO + mA]       = acc[mt][nt][0] * sA + hA;
                Y[(n + 1) * CO + mA] = acc[mt][nt][1] * sA + hA;
            }
            if (wB) {
                Y[n * CO + mB]       = acc[mt][nt][2] * sB + hB;
                Y[(n + 1) * CO + mB] = acc[mt][nt][3] * sB + hB;
            }
        }
    }
}

// ---------------- fused attention + residual + per-head LN + spatial mean ----------------
#define KSTRIDE 68
#define VSTRIDE 66
#define AWARPS  16

__global__ void __launch_bounds__(512)
attn_kernel(const float* __restrict__ qb,    // [n][512]
            const float* __restrict__ kvb,   // [n2][1024]
            const float* __restrict__ resb,  // [n][64]
            const float* __restrict__ lng, const float* __restrict__ lnb,
            float* __restrict__ out) {
    extern __shared__ float sm[];
    float* KS  = sm;                       // 196 * 68
    float* VS  = KS + P2 * KSTRIDE;        // 196 * 66
    float* QS  = VS + P2 * VSTRIDE;        // 16 * 256
    float* PB  = QS + AWARPS * 256;        // 16 * 784
    float* ACC = PB + AWARPS * 784;        // 16 * 64

    int bh = blockIdx.x;
    int b = bh >> 3, h = bh & 7;
    int tid  = threadIdx.x;
    int lane = tid & 31;
    int wid  = tid >> 5;

    const float* kvbase = kvb + (size_t)b * P2 * 1024 + h * 64;
    for (int l = tid; l < P2 * DHEAD; l += 512) {
        int j = l >> 6, d = l & 63;
        const float* kb = kvbase + (size_t)j * 1024;
        KS[j * KSTRIDE + d] = kb[d];
        VS[j * VSTRIDE + d] = kb[512 + d];
    }
    __syncthreads();

    const float* qbase = qb + (size_t)b * P1 * INNER + h * 64;
    const float* rbase = resb + (size_t)b * P1 * 64;

    float* qs = QS + wid * 256;
    float* pb = PB + wid * 784;

    int d0 = 2 * lane, d1 = 2 * lane + 1;
    float lg0 = lng[h * 64 + d0], lb0 = lnb[h * 64 + d0];
    float lg1 = lng[h * 64 + d1], lb1 = lnb[h * 64 + d1];

    float S0 = 0.f, S1 = 0.f;

    for (int c = wid; c < 196; c += AWARPS) {
        int i0 = c * 4;
#pragma unroll
        for (int q = 0; q < 4; q++) {
            float2 qv = *(const float2*)(qbase + (size_t)(i0 + q) * INNER + d0);
            qs[q * 64 + d0] = qv.x;
            qs[q * 64 + d1] = qv.y;
        }
        __syncwarp();

        // ---- phase A: dots + softmax ----
        float loc0[7], loc1[7], loc2[7], loc3[7];
        float mx0 = -1e30f, mx1 = -1e30f, mx2 = -1e30f, mx3 = -1e30f;
        const float4* q0p = (const float4*)(qs);
        const float4* q1p = (const float4*)(qs + 64);
        const float4* q2p = (const float4*)(qs + 128);
        const float4* q3p = (const float4*)(qs + 192);
#pragma unroll
        for (int t = 0; t < 7; t++) {
            int j = lane + t * 32;
            float s0 = 0.f, s1 = 0.f, s2 = 0.f, s3 = 0.f;
            if (j < 196) {
                const float4* kr = (const float4*)(KS + j * KSTRIDE);
#pragma unroll
                for (int g4 = 0; g4 < 16; g4++) {
                    float4 kv4 = kr[g4];
                    float4 a;
                    a = q0p[g4]; s0 += a.x*kv4.x + a.y*kv4.y + a.z*kv4.z + a.w*kv4.w;
                    a = q1p[g4]; s1 += a.x*kv4.x + a.y*kv4.y + a.z*kv4.z + a.w*kv4.w;
                    a = q2p[g4]; s2 += a.x*kv4.x + a.y*kv4.y + a.z*kv4.z + a.w*kv4.w;
                    a = q3p[g4]; s3 += a.x*kv4.x + a.y*kv4.y + a.z*kv4.z + a.w*kv4.w;
                }
                s0 *= 0.125f; s1 *= 0.125f; s2 *= 0.125f; s3 *= 0.125f;
                mx0 = fmaxf(mx0, s0); mx1 = fmaxf(mx1, s1);
                mx2 = fmaxf(mx2, s2); mx3 = fmaxf(mx3, s3);
            }
            loc0[t] = s0; loc1[t] = s1; loc2[t] = s2; loc3[t] = s3;
        }
#pragma unroll
        for (int o = 16; o > 0; o >>= 1) {
            mx0 = fmaxf(mx0, __shfl_xor_sync(0xffffffffu, mx0, o));
            mx1 = fmaxf(mx1, __shfl_xor_sync(0xffffffffu, mx1, o));
            mx2 = fmaxf(mx2, __shfl_xor_sync(0xffffffffu, mx2, o));
            mx3 = fmaxf(mx3, __shfl_xor_sync(0xffffffffu, mx3, o));
        }
        float sm0 = 0.f, sm1 = 0.f, sm2 = 0.f, sm3 = 0.f;
#pragma unroll
        for (int t = 0; t < 7; t++) {
            int j = lane + t * 32;
            if (j < 196) {
                float e0 = __expf(loc0[t] - mx0);
                float e1 = __expf(loc1[t] - mx1);
                float e2 = __expf(loc2[t] - mx2);
                float e3 = __expf(loc3[t] - mx3);
                sm0 += e0; sm1 += e1; sm2 += e2; sm3 += e3;
                ((float4*)pb)[j] = make_float4(e0, e1, e2, e3);
            }
        }
#pragma unroll
        for (int o = 16; o > 0; o >>= 1) {
            sm0 += __shfl_xor_sync(0xffffffffu, sm0, o);
            sm1 += __shfl_xor_sync(0xffffffffu, sm1, o);
            sm2 += __shfl_xor_sync(0xffffffffu, sm2, o);
            sm3 += __shfl_xor_sync(0xffffffffu, sm3, o);
        }
        float inv[4];
        inv[0] = 1.f / sm0; inv[1] = 1.f / sm1; inv[2] = 1.f / sm2; inv[3] = 1.f / sm3;
        __syncwarp();

        // ---- phase B: attn @ V ----
        float aq[4][2];
#pragma unroll
        for (int q = 0; q < 4; q++) { aq[q][0] = 0.f; aq[q][1] = 0.f; }
        const float4* pbv = (const float4*)pb;
        for (int j = 0; j < 196; j++) {
            float4 pv = pbv[j];
            float2 vv = *((const float2*)(VS + j * VSTRIDE + d0));
            aq[0][0] += pv.x * vv.x; aq[0][1] += pv.x * vv.y;
            aq[1][0] += pv.y * vv.x; aq[1][1] += pv.y * vv.y;
            aq[2][0] += pv.z * vv.x; aq[2][1] += pv.z * vv.y;
            aq[3][0] += pv.w * vv.x; aq[3][1] += pv.w * vv.y;
        }

        // ---- residual + per-head LN + running spatial sum ----
#pragma unroll
        for (int q = 0; q < 4; q++) {
            float2 rv = *(const float2*)(rbase + (size_t)(i0 + q) * 64 + d0);
            float o0 = aq[q][0] * inv[q] + rv.x;
            float o1 = aq[q][1] * inv[q] + rv.y;
            float s1v = o0 + o1;
            float s2v = o0 * o0 + o1 * o1;
#pragma unroll
            for (int o = 16; o > 0; o >>= 1) {
                s1v += __shfl_xor_sync(0xffffffffu, s1v, o);
                s2v += __shfl_xor_sync(0xffffffffu, s2v, o);
            }
            float mean = s1v * (1.f / 64.f);
            float var  = fmaxf(s2v * (1.f / 64.f) - mean * mean, 0.f);
            float istd = 1.f / (sqrtf(var) + 1e-5f);
            S0 += (o0 - mean) * istd * lg0 + lb0;
            S1 += (o1 - mean) * istd * lg1 + lb1;
        }
        __syncwarp();
    }

    ACC[wid * 64 + d0] = S0;
    ACC[wid * 64 + d1] = S1;
    __syncthreads();
    if (tid < 64) {
        float s = 0.f;
#pragma unroll
        for (int w = 0; w < AWARPS; w++) s += ACC[w * 64 + tid];
        out[(size_t)bh * 64 + tid] = s * (1.f / 784.f);
    }
}

// ---------------- launch ----------------
extern "C" void kernel_launch(void* const* d_in, const int* in_sizes, int n_in,
                              void* d_out, int out_size) {
    (void)in_sizes; (void)n_in; (void)out_size;
    const float* x      = (const float*)d_in[0];
    const float* w_dwq  = (const float*)d_in[1];
    const float* w_pwq  = (const float*)d_in[2];
    const float* w_dwkv = (const float*)d_in[3];
    const float* w_pwkv = (const float*)d_in[4];
    const float* w_ds   = (const float*)d_in[5];
    const float* ln_g   = (const float*)d_in[6];
    const float* ln_b   = (const float*)d_in[7];
    const float* bnq_g  = (const float*)d_in[8];
    const float* bnq_b  = (const float*)d_in[9];
    const float* bnq_m  = (const float*)d_in[10];
    const float* bnq_v  = (const float*)d_in[11];
    const float* bnkv_g = (const float*)d_in[12];
    const float* bnkv_b = (const float*)d_in[13];
    const float* bnkv_m = (const float*)d_in[14];
    const float* bnkv_v = (const float*)d_in[15];
    const float* bnds_g = (const float*)d_in[16];
    const float* bnds_b = (const float*)d_in[17];
    const float* bnds_m = (const float*)d_in[18];
    const float* bnds_v = (const float*)d_in[19];
    float* out = (float*)d_out;

    float *dq, *dkv, *qbuf, *kvbuf, *resb;
    __nv_bfloat16 *hiq, *loq, *hikv, *lokv, *hix, *lox;
    __nv_bfloat16 *hwq, *lwq, *hwkv, *lwkv, *hwds, *lwds;
    cudaGetSymbolAddress((void**)&dq,   g_dq);
    cudaGetSymbolAddress((void**)&dkv,  g_dkv);
    cudaGetSymbolAddress((void**)&hiq,  g_hiq);
    cudaGetSymbolAddress((void**)&loq,  g_loq);
    cudaGetSymbolAddress((void**)&hikv, g_hikv);
    cudaGetSymbolAddress((void**)&lokv, g_lokv);
    cudaGetSymbolAddress((void**)&hix,  g_hix);
    cudaGetSymbolAddress((void**)&lox,  g_lox);
    cudaGetSymbolAddress((void**)&hwq,  g_hwq);
    cudaGetSymbolAddress((void**)&lwq,  g_lwq);
    cudaGetSymbolAddress((void**)&hwkv, g_hwkv);
    cudaGetSymbolAddress((void**)&lwkv, g_lwkv);
    cudaGetSymbolAddress((void**)&hwds, g_hwds);
    cudaGetSymbolAddress((void**)&lwds, g_lwds);
    cudaGetSymbolAddress((void**)&qbuf, g_q);
    cudaGetSymbolAddress((void**)&kvbuf, g_kv);
    cudaGetSymbolAddress((void**)&resb, g_res);

    // 1) depthwise convs + BN -> [c][n]
    int tot1 = CIN * BATCH * P1;
    dwconv_bn_kernel<<<(tot1 + 255) / 256, 256>>>(
        x, w_dwq, bnq_g, bnq_b, bnq_m, bnq_v, dq, CIN, 28, 28, 28, 28, 1, tot1);
    int tot2 = CIN * BATCH * P2;
    dwconv_bn_kernel<<<(tot2 + 255) / 256, 256>>>(
        x, w_dwkv, bnkv_g, bnkv_b, bnkv_m, bnkv_v, dkv, CIN, 28, 28, 14, 14, 2, tot2);

    // 2) weight + activation bf16 hi/lo splits
    wsplit_kernel<<<(INNER * CIN + 255) / 256, 256>>>(w_pwq, hwq, lwq, INNER * CIN, INNER * CIN);
    wsplit_kernel<<<(2 * INNER * CIN + 255) / 256, 256>>>(w_pwkv, hwkv, lwkv, 2 * INNER * CIN, 2 * INNER * CIN);
    wsplit_kernel<<<(128 * CIN + 255) / 256, 256>>>(w_ds, hwds, lwds, 64 * CIN, 128 * CIN);
    {
        dim3 g(NQ / 32, CIN / 32);
        tsplit_kernel<<<g, dim3(32, 8)>>>(dq, hiq, loq, CIN, NQ);
        dim3 g2(NKV / 32, CIN / 32);
        tsplit_kernel<<<g2, dim3(32, 8)>>>(dkv, hikv, lokv, CIN, NKV);
        dim3 g3((P1 + 31) / 32, CIN / 32, BATCH);
        tsplit_x_kernel<<<g3, dim3(32, 8)>>>(x, hix, lox);
    }

    // 3) tensor-core GEMMs (output [n][co])
    size_t gemm_smem = (size_t)4 * 128 * ASTRIDE * sizeof(__nv_bfloat16);  // 73728
    cudaFuncSetAttribute(mma_gemm_kernel, cudaFuncAttributeMaxDynamicSharedMemorySize, (int)gemm_smem);
    {
        dim3 gq(NQ / 128, INNER / 128);         // (392, 4)
        mma_gemm_kernel<<<gq, 256, gemm_smem>>>(hwq, lwq, hiq, loq, qbuf, INNER, NQ,
                                                nullptr, nullptr, nullptr, nullptr);
        dim3 gkv(NKV / 128, (2 * INNER) / 128); // (98, 8)
        mma_gemm_kernel<<<gkv, 256, gemm_smem>>>(hwkv, lwkv, hikv, lokv, kvbuf, 2 * INNER, NKV,
                                                 nullptr, nullptr, nullptr, nullptr);
        dim3 gr(NQ / 128, 1);                   // residual, CO=64 (padded weights to 128)
        mma_gemm_kernel<<<gr, 256, gemm_smem>>>(hwds, lwds, hix, lox, resb, DHEAD, NQ,
                                                bnds_g, bnds_b, bnds_m, bnds_v);
    }

    // 4) fused attention + residual + LN + mean
    size_t smem = (size_t)(P2 * KSTRIDE + P2 * VSTRIDE + AWARPS * 256 + AWARPS * 784 + AWARPS * 64) * sizeof(float);
    cudaFuncSetAttribute(attn_kernel, cudaFuncAttributeMaxDynamicSharedMemorySize, (int)smem);
    attn_kernel<<<BATCH * NHEAD, 512, smem>>>(qbuf, kvbuf, resb, ln_g, ln_b, out);
}

// round 5
// speedup vs baseline: 2.5966x; 1.9335x over previous
#include <cuda_runtime.h>
#include <cuda_bf16.h>
#include <math.h>
#include <stdint.h>

#define BATCH 64
#define CIN   640
#define P1    784
#define P2    196
#define NQ    (BATCH * P1)   // 50176
#define NKV   (BATCH * P2)   // 12544
#define INNER 512
#define NHEAD 8
#define DHEAD 64
#define ASTRIDE 72           // smem tile row stride (bf16): 144B, ldmatrix conflict-free
#define TILE_ELEMS (128 * ASTRIDE)   // 9216 bf16 = 18432 B

// ---------------- scratch ----------------
__device__ __nv_bfloat16  g_hiq [NQ * CIN];
__device__ __nv_bfloat16  g_loq [NQ * CIN];
__device__ __nv_bfloat16  g_hikv[NKV * CIN];
__device__ __nv_bfloat16  g_lokv[NKV * CIN];
__device__ __nv_bfloat16  g_hix [NQ * CIN];
__device__ __nv_bfloat16  g_lox [NQ * CIN];
__device__ __nv_bfloat16  g_hwq [INNER * CIN];
__device__ __nv_bfloat16  g_lwq [INNER * CIN];
__device__ __nv_bfloat16  g_hwkv[2 * INNER * CIN];
__device__ __nv_bfloat16  g_lwkv[2 * INNER * CIN];
__device__ __nv_bfloat16  g_hwds[128 * CIN];
__device__ __nv_bfloat16  g_lwds[128 * CIN];
__device__ float          g_q   [NQ * INNER];
__device__ float          g_kv  [NKV * 2 * INNER];
__device__ float          g_res [NQ * DHEAD];

// =================== helpers ===================
__device__ __forceinline__ uint32_t smem_u32(const void* p) {
    uint32_t a;
    asm("{ .reg .u64 t; cvta.to.shared.u64 t, %1; cvt.u32.u64 %0, t; }" : "=r"(a) : "l"(p));
    return a;
}
#define CP_ASYNC16(sa, ga) \
    asm volatile("cp.async.cg.shared.global [%0], [%1], 16;" :: "r"(sa), "l"(ga))
#define CP_COMMIT() asm volatile("cp.async.commit_group;")
#define CP_WAIT(n)  asm volatile("cp.async.wait_group %0;" :: "n"(n))

// ---------------- merged weight split (all three weight tensors) ----------------
#define WQ_N   (INNER * CIN)
#define WKV_N  (2 * INNER * CIN)
#define WDS_N  (128 * CIN)
#define WDS_SRC (64 * CIN)
__global__ void wsplit_all_kernel(const float* __restrict__ wq,
                                  const float* __restrict__ wkv,
                                  const float* __restrict__ wds,
                                  __nv_bfloat16* __restrict__ hwq, __nv_bfloat16* __restrict__ lwq,
                                  __nv_bfloat16* __restrict__ hwkv, __nv_bfloat16* __restrict__ lwkv,
                                  __nv_bfloat16* __restrict__ hwds, __nv_bfloat16* __restrict__ lwds) {
    int i = blockIdx.x * blockDim.x + threadIdx.x;
    float v;
    __nv_bfloat16 *hp, *lp;
    int o;
    if (i < WQ_N) {
        v = wq[i]; hp = hwq; lp = lwq; o = i;
    } else if (i < WQ_N + WKV_N) {
        o = i - WQ_N; v = wkv[o]; hp = hwkv; lp = lwkv;
    } else if (i < WQ_N + WKV_N + WDS_N) {
        o = i - WQ_N - WKV_N;
        v = (o < WDS_SRC) ? wds[o] : 0.f;
        hp = hwds; lp = lwds;
    } else return;
    __nv_bfloat16 h = __float2bfloat16(v);
    hp[o] = h;
    lp[o] = __float2bfloat16(v - __bfloat162float(h));
}

// ---------------- fused dwconv3x3 + BN + transpose + bf16 hi/lo split ----------------
// x: [b][C][28][28]; out hi/lo: [(b*P + p)][C]
__global__ void dwsplit_kernel(const float* __restrict__ x,
                               const float* __restrict__ w,
                               const float* __restrict__ bg, const float* __restrict__ bb,
                               const float* __restrict__ bm, const float* __restrict__ bv,
                               __nv_bfloat16* __restrict__ hi, __nv_bfloat16* __restrict__ lo,
                               int OH, int OW, int stride, int P) {
    __shared__ float t[64][33];
    int b  = blockIdx.z;
    int c0 = blockIdx.y * 64;
    int p0 = blockIdx.x * 32;
    int tx = threadIdx.x, ty = threadIdx.y;   // (32,8)
    const int H = 28, W = 28;
    int p = p0 + tx;
    int oy = p / OW, ox = p % OW;
    int iy0 = oy * stride - 1, ix0 = ox * stride - 1;
#pragma unroll
    for (int r = 0; r < 8; r++) {
        int c = c0 + ty + r * 8;
        float val = 0.f;
        if (p < P) {
            const float* xb = x + ((size_t)(b * CIN + c)) * (H * W);
            const float* wc = w + c * 9;
            float acc = 0.f;
#pragma unroll
            for (int dy = 0; dy < 3; dy++) {
                int iy = iy0 + dy;
                if (iy < 0 || iy >= H) continue;
#pragma unroll
                for (int dx = 0; dx < 3; dx++) {
                    int ix = ix0 + dx;
                    if (ix < 0 || ix >= W) continue;
                    acc += xb[iy * W + ix] * wc[dy * 3 + dx];
                }
            }
            float inv = bg[c] * rsqrtf(bv[c] + 1e-5f);
            val = (acc - bm[c]) * inv + bb[c];
        }
        t[ty + r * 8][tx] = val;
    }
    __syncthreads();
#pragma unroll
    for (int r = 0; r < 4; r++) {
        int nl = ty + r * 8;
        int pp = p0 + nl;
        if (pp < P) {
            size_t n = (size_t)b * P + pp;
            float v0 = t[2 * tx][nl], v1 = t[2 * tx + 1][nl];
            __nv_bfloat16 h0 = __float2bfloat16(v0), h1 = __float2bfloat16(v1);
            __nv_bfloat16 l0 = __float2bfloat16(v0 - __bfloat162float(h0));
            __nv_bfloat16 l1 = __float2bfloat16(v1 - __bfloat162float(h1));
            *(__nv_bfloat162*)(hi + n * CIN + c0 + 2 * tx) = __halves2bfloat162(h0, h1);
            *(__nv_bfloat162*)(lo + n * CIN + c0 + 2 * tx) = __halves2bfloat162(l0, l1);
        }
    }
}

// ---------------- per-batch transpose of raw x + hi/lo split (residual B operand) --------
__global__ void tsplit_x_kernel(const float* __restrict__ X,
                                __nv_bfloat16* __restrict__ hi, __nv_bfloat16* __restrict__ lo) {
    __shared__ float t[32][33];
    int b  = blockIdx.z;
    int p0 = blockIdx.x * 32, c0 = blockIdx.y * 32;
    int tx = threadIdx.x, ty = threadIdx.y;  // (32,8)
#pragma unroll
    for (int r = 0; r < 4; r++) {
        int c = c0 + ty + r * 8;
        int p = p0 + tx;
        t[ty + r * 8][tx] = (p < P1) ? X[((size_t)b * CIN + c) * P1 + p] : 0.f;
    }
    __syncthreads();
#pragma unroll
    for (int r = 0; r < 4; r++) {
        int p = p0 + ty + r * 8;
        int c = c0 + tx;
        if (p < P1) {
            float v = t[tx][ty + r * 8];
            __nv_bfloat16 h = __float2bfloat16(v);
            size_t o = ((size_t)b * P1 + p) * CIN + c;
            hi[o] = h;
            lo[o] = __float2bfloat16(v - __bfloat162float(h));
        }
    }
}

// ---------------- fused 3-segment mma.sync bf16 GEMM ----------------
// acc = hiW*hiX + loW*hiX + hiW*loX over K=640 (10 chunks of 64)
// Y[n][CO] via smem-staged coalesced epilogue (+ optional BN on m)
__global__ void __launch_bounds__(256)
mma_gemm_kernel(const __nv_bfloat16* __restrict__ hiW, const __nv_bfloat16* __restrict__ loW,
                const __nv_bfloat16* __restrict__ hiX, const __nv_bfloat16* __restrict__ loX,
                float* __restrict__ Y, int CO, int N,
                const float* __restrict__ bg, const float* __restrict__ bb,
                const float* __restrict__ bm, const float* __restrict__ bv) {
    extern __shared__ __nv_bfloat16 smem[];   // 8 tiles of TILE_ELEMS (2 bufs x {hiA,loA,hiB,loB})

    int tid = threadIdx.x, lane = tid & 31, wid = tid >> 5;
    int warp_m = wid >> 2, warp_n = wid & 3;
    int m0 = blockIdx.x * 128, n0 = blockIdx.y * 128;   // m fast -> B-tile L2 reuse

    int lrow = tid >> 1, lhalf = tid & 1;

    float acc[4][4][4];
#pragma unroll
    for (int i = 0; i < 4; i++)
#pragma unroll
        for (int j = 0; j < 4; j++)
#pragma unroll
            for (int k = 0; k < 4; k++) acc[i][j][k] = 0.f;

    int a_row = warp_m * 64 + ((lane & 7) | (((lane >> 3) & 1) << 3));
    int a_off = a_row * (ASTRIDE * 2) + (lane >> 4) * 16;
    int b_row = warp_n * 32 + (lane & 7);
    int b_off = b_row * (ASTRIDE * 2) + ((lane >> 3) & 1) * 16;

#define LOADC(ch, buf) do { \
        int _kk = (ch) * 64; \
        const __nv_bfloat16* _p0 = hiW + (size_t)(m0 + lrow) * CIN + _kk + lhalf * 32; \
        const __nv_bfloat16* _p1 = loW + (size_t)(m0 + lrow) * CIN + _kk + lhalf * 32; \
        const __nv_bfloat16* _p2 = hiX + (size_t)(n0 + lrow) * CIN + _kk + lhalf * 32; \
        const __nv_bfloat16* _p3 = loX + (size_t)(n0 + lrow) * CIN + _kk + lhalf * 32; \
        uint32_t _b = smem_u32(smem) + (uint32_t)(buf) * 4u * 18432u + lrow * 144u + lhalf * 64u; \
        _Pragma("unroll") \
        for (int _i = 0; _i < 4; _i++) { \
            CP_ASYNC16(_b + 0u * 18432u + _i * 16, _p0 + _i * 8); \
            CP_ASYNC16(_b + 1u * 18432u + _i * 16, _p1 + _i * 8); \
            CP_ASYNC16(_b + 2u * 18432u + _i * 16, _p2 + _i * 8); \
            CP_ASYNC16(_b + 3u * 18432u + _i * 16, _p3 + _i * 8); \
        } \
        CP_COMMIT(); \
    } while (0)

    LOADC(0, 0);

    for (int s = 0; s < 10; s++) {
        int buf = s & 1;
        if (s + 1 < 10) {
            LOADC(s + 1, buf ^ 1);
            CP_WAIT(1);
        } else {
            CP_WAIT(0);
        }
        __syncthreads();

        uint32_t hiA = smem_u32(smem) + (uint32_t)buf * 4u * 18432u;
        uint32_t loA = hiA + 18432u, hiB = hiA + 2u * 18432u, loB = hiA + 3u * 18432u;
        uint32_t hiAo = hiA + a_off, loAo = loA + a_off;
        uint32_t hiBo = hiB + b_off, loBo = loB + b_off;
#pragma unroll
        for (int ks = 0; ks < 4; ks++) {
            uint32_t ah[4][4], al[4][4], bh[4][2], bl[4][2];
#pragma unroll
            for (int mt = 0; mt < 4; mt++) {
                uint32_t off = mt * 16 * (ASTRIDE * 2) + ks * 32;
                asm volatile("ldmatrix.sync.aligned.m8n8.x4.shared.b16 {%0,%1,%2,%3}, [%4];"
                             : "=r"(ah[mt][0]), "=r"(ah[mt][1]), "=r"(ah[mt][2]), "=r"(ah[mt][3])
                             : "r"(hiAo + off));
                asm volatile("ldmatrix.sync.aligned.m8n8.x4.shared.b16 {%0,%1,%2,%3}, [%4];"
                             : "=r"(al[mt][0]), "=r"(al[mt][1]), "=r"(al[mt][2]), "=r"(al[mt][3])
                             : "r"(loAo + off));
            }
#pragma unroll
            for (int nt = 0; nt < 4; nt++) {
                uint32_t off = nt * 8 * (ASTRIDE * 2) + ks * 32;
                asm volatile("ldmatrix.sync.aligned.m8n8.x2.shared.b16 {%0,%1}, [%2];"
                             : "=r"(bh[nt][0]), "=r"(bh[nt][1]) : "r"(hiBo + off));
                asm volatile("ldmatrix.sync.aligned.m8n8.x2.shared.b16 {%0,%1}, [%2];"
                             : "=r"(bl[nt][0]), "=r"(bl[nt][1]) : "r"(loBo + off));
            }
#define MMA(acr, af, bf) \
            asm volatile("mma.sync.aligned.m16n8k16.row.col.f32.bf16.bf16.f32 " \
                "{%0,%1,%2,%3}, {%4,%5,%6,%7}, {%8,%9}, {%0,%1,%2,%3};" \
                : "+f"((acr)[0]), "+f"((acr)[1]), "+f"((acr)[2]), "+f"((acr)[3]) \
                : "r"((af)[0]), "r"((af)[1]), "r"((af)[2]), "r"((af)[3]), \
                  "r"((bf)[0]), "r"((bf)[1]))
#pragma unroll
            for (int mt = 0; mt < 4; mt++)
#pragma unroll
                for (int nt = 0; nt < 4; nt++) {
                    MMA(acc[mt][nt], ah[mt], bh[nt]);
                    MMA(acc[mt][nt], al[mt], bh[nt]);
                    MMA(acc[mt][nt], ah[mt], bl[nt]);
                }
        }
        __syncthreads();
    }

    // -------- smem-staged epilogue: stage [n][m] tile, then coalesced float4 stores --------
    float* st = (float*)smem;     // 128 x 132 floats = 67584 B (< 147456)
    int g = lane >> 2, t4 = lane & 3;
#pragma unroll
    for (int mt = 0; mt < 4; mt++) {
        int mAl = warp_m * 64 + mt * 16 + g;
        int mBl = mAl + 8;
        int mA = m0 + mAl, mB = m0 + mBl;
        float sA = 1.f, hA = 0.f, sB = 1.f, hB = 0.f;
        if (bg) {
            if (mA < CO) { float iv = bg[mA] * rsqrtf(bv[mA] + 1e-5f); sA = iv; hA = bb[mA] - bm[mA] * iv; }
            if (mB < CO) { float iv = bg[mB] * rsqrtf(bv[mB] + 1e-5f); sB = iv; hB = bb[mB] - bm[mB] * iv; }
        }
#pragma unroll
        for (int nt = 0; nt < 4; nt++) {
            int nl = warp_n * 32 + nt * 8 + 2 * t4;
            st[nl * 132 + mAl]       = acc[mt][nt][0] * sA + hA;
            st[(nl + 1) * 132 + mAl] = acc[mt][nt][1] * sA + hA;
            st[nl * 132 + mBl]       = acc[mt][nt][2] * sB + hB;
            st[(nl + 1) * 132 + mBl] = acc[mt][nt][3] * sB + hB;
        }
    }
    __syncthreads();
    int row = tid >> 1, half = tid & 1;
    int cmax = CO - m0; if (cmax > 128) cmax = 128;
    int cstart = half * (cmax >> 1), cend = cstart + (cmax >> 1);
    float* dst = Y + (size_t)(n0 + row) * CO + m0;
    for (int col = cstart; col < cend; col += 4)
        *(float4*)(dst + col) = *(float4*)(st + row * 132 + col);
#undef LOADC
#undef MMA
}

// ---------------- fused attention + residual + per-head LN + spatial mean ----------------
#define KSTRIDE 68
#define VSTRIDE 66
#define AWARPS  12
#define QROWS   8     // queries per warp-group

__global__ void __launch_bounds__(384)
attn_kernel(const float* __restrict__ qb,    // [n][512]
            const float* __restrict__ kvb,   // [n2][1024]
            const float* __restrict__ resb,  // [n][64]
            const float* __restrict__ lng, const float* __restrict__ lnb,
            float* __restrict__ out) {
    extern __shared__ float sm[];
    float* KS  = sm;                         // 196*68 = 13328
    float* VS  = KS + P2 * KSTRIDE;          // 196*66 = 12936
    float* QS  = VS + P2 * VSTRIDE;          // 12*544 = 6528
    float* PB  = QS + AWARPS * (QROWS * 68); // 12*1600 = 19200
    float* ACC = PB + AWARPS * (QROWS * 200);// 12*64

    int bh = blockIdx.x;
    int b = bh >> 3, h = bh & 7;
    int tid  = threadIdx.x;
    int lane = tid & 31;
    int wid  = tid >> 5;

    const float* kvbase = kvb + (size_t)b * P2 * 1024 + h * 64;
    for (int l = tid; l < P2 * DHEAD; l += 384) {
        int j = l >> 6, d = l & 63;
        const float* kb = kvbase + (size_t)j * 1024;
        KS[j * KSTRIDE + d] = kb[d];
        VS[j * VSTRIDE + d] = kb[512 + d];
    }
    __syncthreads();

    const float* qbase = qb + (size_t)b * P1 * INNER + h * 64;
    const float* rbase = resb + (size_t)b * P1 * 64;

    float* qs  = QS + wid * (QROWS * 68);
    float* pbw = PB + wid * (QROWS * 200);

    int d0 = 2 * lane, d1 = 2 * lane + 1;
    float lg0 = lng[h * 64 + d0], lb0 = lnb[h * 64 + d0];
    float lg1 = lng[h * 64 + d1], lb1 = lnb[h * 64 + d1];

    float S0 = 0.f, S1 = 0.f;

    int qr = lane >> 2, qseg = lane & 3;   // q staging: 4 lanes per row, 16 floats each

    for (int c = wid; c < 98; c += AWARPS) {
        int i0 = c * 8;
        // stage 8 query rows
        {
            const float4* src = (const float4*)(qbase + (size_t)(i0 + qr) * INNER + qseg * 16);
            float4* dst = (float4*)(qs + qr * 68 + qseg * 16);
#pragma unroll
            for (int k = 0; k < 4; k++) dst[k] = src[k];
        }
        __syncwarp();

        // ---- phase A: logits ----
        float loc[7][8];
#pragma unroll
        for (int t = 0; t < 7; t++)
#pragma unroll
            for (int q = 0; q < 8; q++) loc[t][q] = 0.f;

#pragma unroll 1
        for (int g4 = 0; g4 < 16; g4++) {
            float4 qv[8];
#pragma unroll
            for (int q = 0; q < 8; q++) qv[q] = *(const float4*)(qs + q * 68 + g4 * 4);
#pragma unroll
            for (int t = 0; t < 7; t++) {
                if (t < 6 || lane < 4) {
                    int j = lane + t * 32;
                    float4 k4 = *(const float4*)(KS + j * KSTRIDE + g4 * 4);
#pragma unroll
                    for (int q = 0; q < 8; q++)
                        loc[t][q] += qv[q].x * k4.x + qv[q].y * k4.y + qv[q].z * k4.z + qv[q].w * k4.w;
                }
            }
        }

        // ---- softmax ----
        float mx[8], sum[8], inv[8];
#pragma unroll
        for (int q = 0; q < 8; q++) mx[q] = -1e30f;
#pragma unroll
        for (int t = 0; t < 7; t++)
            if (t < 6 || lane < 4)
#pragma unroll
                for (int q = 0; q < 8; q++) {
                    loc[t][q] *= 0.125f;
                    mx[q] = fmaxf(mx[q], loc[t][q]);
                }
#pragma unroll
        for (int q = 0; q < 8; q++)
#pragma unroll
            for (int o = 16; o > 0; o >>= 1)
                mx[q] = fmaxf(mx[q], __shfl_xor_sync(0xffffffffu, mx[q], o));
#pragma unroll
        for (int q = 0; q < 8; q++) sum[q] = 0.f;
#pragma unroll
        for (int t = 0; t < 7; t++) {
            int j = lane + t * 32;
            if (t < 6 || lane < 4) {
#pragma unroll
                for (int q = 0; q < 8; q++) {
                    float e = __expf(loc[t][q] - mx[q]);
                    sum[q] += e;
                    pbw[q * 200 + j] = e;
                }
            }
        }
#pragma unroll
        for (int q = 0; q < 8; q++) {
#pragma unroll
            for (int o = 16; o > 0; o >>= 1)
                sum[q] += __shfl_xor_sync(0xffffffffu, sum[q], o);
            inv[q] = 1.f / sum[q];
        }
        __syncwarp();

        // ---- phase B: P @ V ----
        float aq[8][2];
#pragma unroll
        for (int q = 0; q < 8; q++) { aq[q][0] = 0.f; aq[q][1] = 0.f; }
#pragma unroll 2
        for (int j = 0; j < 196; j++) {
            float2 vv = *(const float2*)(VS + j * VSTRIDE + d0);
#pragma unroll
            for (int q = 0; q < 8; q++) {
                float p = pbw[q * 200 + j];
                aq[q][0] += p * vv.x;
                aq[q][1] += p * vv.y;
            }
        }

        // ---- residual + per-head LN + running spatial sum ----
#pragma unroll
        for (int q = 0; q < 8; q++) {
            float2 rv = *(const float2*)(rbase + (size_t)(i0 + q) * 64 + d0);
            float o0 = aq[q][0] * inv[q] + rv.x;
            float o1 = aq[q][1] * inv[q] + rv.y;
            float s1v = o0 + o1;
            float s2v = o0 * o0 + o1 * o1;
#pragma unroll
            for (int o = 16; o > 0; o >>= 1) {
                s1v += __shfl_xor_sync(0xffffffffu, s1v, o);
                s2v += __shfl_xor_sync(0xffffffffu, s2v, o);
            }
            float mean = s1v * (1.f / 64.f);
            float var  = fmaxf(s2v * (1.f / 64.f) - mean * mean, 0.f);
            float istd = 1.f / (sqrtf(var) + 1e-5f);
            S0 += (o0 - mean) * istd * lg0 + lb0;
            S1 += (o1 - mean) * istd * lg1 + lb1;
        }
        __syncwarp();
    }

    ACC[wid * 64 + d0] = S0;
    ACC[wid * 64 + d1] = S1;
    __syncthreads();
    if (tid < 64) {
        float s = 0.f;
#pragma unroll
        for (int w = 0; w < AWARPS; w++) s += ACC[w * 64 + tid];
        out[(size_t)bh * 64 + tid] = s * (1.f / 784.f);
    }
}

// ---------------- launch ----------------
extern "C" void kernel_launch(void* const* d_in, const int* in_sizes, int n_in,
                              void* d_out, int out_size) {
    (void)in_sizes; (void)n_in; (void)out_size;
    const float* x      = (const float*)d_in[0];
    const float* w_dwq  = (const float*)d_in[1];
    const float* w_pwq  = (const float*)d_in[2];
    const float* w_dwkv = (const float*)d_in[3];
    const float* w_pwkv = (const float*)d_in[4];
    const float* w_ds   = (const float*)d_in[5];
    const float* ln_g   = (const float*)d_in[6];
    const float* ln_b   = (const float*)d_in[7];
    const float* bnq_g  = (const float*)d_in[8];
    const float* bnq_b  = (const float*)d_in[9];
    const float* bnq_m  = (const float*)d_in[10];
    const float* bnq_v  = (const float*)d_in[11];
    const float* bnkv_g = (const float*)d_in[12];
    const float* bnkv_b = (const float*)d_in[13];
    const float* bnkv_m = (const float*)d_in[14];
    const float* bnkv_v = (const float*)d_in[15];
    const float* bnds_g = (const float*)d_in[16];
    const float* bnds_b = (const float*)d_in[17];
    const float* bnds_m = (const float*)d_in[18];
    const float* bnds_v = (const float*)d_in[19];
    float* out = (float*)d_out;

    float *qbuf, *kvbuf, *resb;
    __nv_bfloat16 *hiq, *loq, *hikv, *lokv, *hix, *lox;
    __nv_bfloat16 *hwq, *lwq, *hwkv, *lwkv, *hwds, *lwds;
    cudaGetSymbolAddress((void**)&hiq,  g_hiq);
    cudaGetSymbolAddress((void**)&loq,  g_loq);
    cudaGetSymbolAddress((void**)&hikv, g_hikv);
    cudaGetSymbolAddress((void**)&lokv, g_lokv);
    cudaGetSymbolAddress((void**)&hix,  g_hix);
    cudaGetSymbolAddress((void**)&lox,  g_lox);
    cudaGetSymbolAddress((void**)&hwq,  g_hwq);
    cudaGetSymbolAddress((void**)&lwq,  g_lwq);
    cudaGetSymbolAddress((void**)&hwkv, g_hwkv);
    cudaGetSymbolAddress((void**)&lwkv, g_lwkv);
    cudaGetSymbolAddress((void**)&hwds, g_hwds);
    cudaGetSymbolAddress((void**)&lwds, g_lwds);
    cudaGetSymbolAddress((void**)&qbuf, g_q);
    cudaGetSymbolAddress((void**)&kvbuf, g_kv);
    cudaGetSymbolAddress((void**)&resb, g_res);

    // #1: all weight splits (independent of everything else)
    {
        int tot = WQ_N + WKV_N + WDS_N;
        wsplit_all_kernel<<<(tot + 255) / 256, 256>>>(w_pwq, w_pwkv, w_ds,
                                                      hwq, lwq, hwkv, lwkv, hwds, lwds);
    }
    // #2, #3: fused dwconv+BN+transpose+split
    {
        dim3 gq((P1 + 31) / 32, CIN / 64, BATCH);
        dwsplit_kernel<<<gq, dim3(32, 8)>>>(x, w_dwq, bnq_g, bnq_b, bnq_m, bnq_v,
                                            hiq, loq, 28, 28, 1, P1);
        dim3 gkv((P2 + 31) / 32, CIN / 64, BATCH);
        dwsplit_kernel<<<gkv, dim3(32, 8)>>>(x, w_dwkv, bnkv_g, bnkv_b, bnkv_m, bnkv_v,
                                             hikv, lokv, 14, 14, 2, P2);
    }
    // #4: q GEMM (profiled launch), #5: kv GEMM
    size_t gemm_smem = (size_t)8 * TILE_ELEMS * sizeof(__nv_bfloat16);  // 147456
    cudaFuncSetAttribute(mma_gemm_kernel, cudaFuncAttributeMaxDynamicSharedMemorySize, (int)gemm_smem);
    {
        dim3 gq(INNER / 128, NQ / 128);          // (4, 392) m fast
        mma_gemm_kernel<<<gq, 256, gemm_smem>>>(hwq, lwq, hiq, loq, qbuf, INNER, NQ,
                                                nullptr, nullptr, nullptr, nullptr);
        dim3 gkv((2 * INNER) / 128, NKV / 128);  // (8, 98)
        mma_gemm_kernel<<<gkv, 256, gemm_smem>>>(hwkv, lwkv, hikv, lokv, kvbuf, 2 * INNER, NKV,
                                                 nullptr, nullptr, nullptr, nullptr);
    }
    // #6: x transpose+split for residual, #7: residual GEMM + BN
    {
        dim3 g3((P1 + 31) / 32, CIN / 32, BATCH);
        tsplit_x_kernel<<<g3, dim3(32, 8)>>>(x, hix, lox);
        dim3 gr(1, NQ / 128);
        mma_gemm_kernel<<<gr, 256, gemm_smem>>>(hwds, lwds, hix, lox, resb, DHEAD, NQ,
                                                bnds_g, bnds_b, bnds_m, bnds_v);
    }
    // #8: fused attention
    size_t smem = (size_t)(P2 * KSTRIDE + P2 * VSTRIDE + AWARPS * (QROWS * 68)
                           + AWARPS * (QROWS * 200) + AWARPS * 64) * sizeof(float);
    cudaFuncSetAttribute(attn_kernel, cudaFuncAttributeMaxDynamicSharedMemorySize, (int)smem);
    attn_kernel<<<BATCH * NHEAD, 384, smem>>>(qbuf, kvbuf, resb, ln_g, ln_b, out);
}

// round 6
// speedup vs baseline: 4.2948x; 1.6540x over previous
#include <cuda_runtime.h>
#include <cuda_bf16.h>
#include <math.h>
#include <stdint.h>

#define BATCH 64
#define CIN   640
#define P1    784
#define P2    196
#define NQ    (BATCH * P1)   // 50176
#define NKV   (BATCH * P2)   // 12544
#define INNER 512
#define NHEAD 8
#define DHEAD 64

// GEMM tiling: K-chunk 32, tile rows 128, row stride 40 bf16 (80B)
#define KC        32
#define RSTRIDE   40
#define TILE_B    (128 * RSTRIDE * 2)   // 10240 bytes per tile
#define STAGE_B   (4 * TILE_B)          // 40960 bytes per stage
#define NCHUNK    (CIN / KC)            // 20

// ---------------- scratch ----------------
__device__ __nv_bfloat16  g_hiq [NQ * CIN];
__device__ __nv_bfloat16  g_loq [NQ * CIN];
__device__ __nv_bfloat16  g_hikv[NKV * CIN];
__device__ __nv_bfloat16  g_lokv[NKV * CIN];
__device__ __nv_bfloat16  g_hix [NQ * CIN];
__device__ __nv_bfloat16  g_lox [NQ * CIN];
__device__ __nv_bfloat16  g_hwq [INNER * CIN];
__device__ __nv_bfloat16  g_lwq [INNER * CIN];
__device__ __nv_bfloat16  g_hwkv[2 * INNER * CIN];
__device__ __nv_bfloat16  g_lwkv[2 * INNER * CIN];
__device__ __nv_bfloat16  g_hwds[128 * CIN];
__device__ __nv_bfloat16  g_lwds[128 * CIN];
__device__ float          g_q   [NQ * INNER];
__device__ float          g_kv  [NKV * 2 * INNER];
__device__ float          g_res [NQ * DHEAD];

// =================== helpers ===================
__device__ __forceinline__ uint32_t smem_u32(const void* p) {
    uint32_t a;
    asm("{ .reg .u64 t; cvta.to.shared.u64 t, %1; cvt.u32.u64 %0, t; }" : "=r"(a) : "l"(p));
    return a;
}
#define CP_ASYNC16(sa, ga) \
    asm volatile("cp.async.cg.shared.global [%0], [%1], 16;" :: "r"(sa), "l"(ga))
#define CP_COMMIT() asm volatile("cp.async.commit_group;")
#define CP_WAIT(n)  asm volatile("cp.async.wait_group %0;" :: "n"(n))

#define LDMX4(r, addr) \
    asm volatile("ldmatrix.sync.aligned.m8n8.x4.shared.b16 {%0,%1,%2,%3}, [%4];" \
        : "=r"((r)[0]), "=r"((r)[1]), "=r"((r)[2]), "=r"((r)[3]) : "r"(addr))
#define LDMX2(r, addr) \
    asm volatile("ldmatrix.sync.aligned.m8n8.x2.shared.b16 {%0,%1}, [%2];" \
        : "=r"((r)[0]), "=r"((r)[1]) : "r"(addr))
#define MMA_BF16(c, a, bb_) \
    asm volatile("mma.sync.aligned.m16n8k16.row.col.f32.bf16.bf16.f32 " \
        "{%0,%1,%2,%3}, {%4,%5,%6,%7}, {%8,%9}, {%0,%1,%2,%3};" \
        : "+f"((c)[0]), "+f"((c)[1]), "+f"((c)[2]), "+f"((c)[3]) \
        : "r"((a)[0]), "r"((a)[1]), "r"((a)[2]), "r"((a)[3]), "r"((bb_)[0]), "r"((bb_)[1]))

__device__ __forceinline__ uint32_t pack_bf16(__nv_bfloat16 a, __nv_bfloat16 b) {
    __nv_bfloat162 v;
    v.x = a; v.y = b;
    return *reinterpret_cast<uint32_t*>(&v);
}
__device__ __forceinline__ void split2(float a, float b, uint32_t& hi, uint32_t& lo) {
    __nv_bfloat16 ha = __float2bfloat16(a), hb = __float2bfloat16(b);
    __nv_bfloat16 la = __float2bfloat16(a - __bfloat162float(ha));
    __nv_bfloat16 lb = __float2bfloat16(b - __bfloat162float(hb));
    hi = pack_bf16(ha, hb);
    lo = pack_bf16(la, lb);
}

// ---------------- merged weight split ----------------
#define WQ_N   (INNER * CIN)
#define WKV_N  (2 * INNER * CIN)
#define WDS_N  (128 * CIN)
#define WDS_SRC (64 * CIN)
__global__ void wsplit_all_kernel(const float* __restrict__ wq,
                                  const float* __restrict__ wkv,
                                  const float* __restrict__ wds,
                                  __nv_bfloat16* __restrict__ hwq, __nv_bfloat16* __restrict__ lwq,
                                  __nv_bfloat16* __restrict__ hwkv, __nv_bfloat16* __restrict__ lwkv,
                                  __nv_bfloat16* __restrict__ hwds, __nv_bfloat16* __restrict__ lwds) {
    int i = blockIdx.x * blockDim.x + threadIdx.x;
    float v;
    __nv_bfloat16 *hp, *lp;
    int o;
    if (i < WQ_N) {
        v = wq[i]; hp = hwq; lp = lwq; o = i;
    } else if (i < WQ_N + WKV_N) {
        o = i - WQ_N; v = wkv[o]; hp = hwkv; lp = lwkv;
    } else if (i < WQ_N + WKV_N + WDS_N) {
        o = i - WQ_N - WKV_N;
        v = (o < WDS_SRC) ? wds[o] : 0.f;
        hp = hwds; lp = lwds;
    } else return;
    __nv_bfloat16 h = __float2bfloat16(v);
    hp[o] = h;
    lp[o] = __float2bfloat16(v - __bfloat162float(h));
}

// ---------------- merged prep: dwconv-q / dwconv-kv / x-transpose, all + hi/lo split ------
// grid (25, 20, 192) block (32,8)
__global__ void prep_kernel(const float* __restrict__ x,
                            const float* __restrict__ wdwq,
                            const float* __restrict__ qg, const float* __restrict__ qb_,
                            const float* __restrict__ qm, const float* __restrict__ qv,
                            const float* __restrict__ wdwkv,
                            const float* __restrict__ kg, const float* __restrict__ kb_,
                            const float* __restrict__ km, const float* __restrict__ kv_,
                            __nv_bfloat16* __restrict__ hiq, __nv_bfloat16* __restrict__ loq,
                            __nv_bfloat16* __restrict__ hikv, __nv_bfloat16* __restrict__ lokv,
                            __nv_bfloat16* __restrict__ hix, __nv_bfloat16* __restrict__ lox) {
    __shared__ float t[64][33];
    int z = blockIdx.z;
    int tx = threadIdx.x, ty = threadIdx.y;
    const int H = 28, W = 28;

    if (z < 128) {
        // depthwise conv + BN + transpose + split
        bool isq = z < 64;
        if (blockIdx.y >= 10) return;
        if (!isq && blockIdx.x >= 7) return;
        int b = isq ? z : z - 64;
        int P = isq ? P1 : P2;
        int OW = isq ? 28 : 14;
        int stride = isq ? 1 : 2;
        const float* w = isq ? wdwq : wdwkv;
        const float* bg = isq ? qg : kg;
        const float* bbp = isq ? qb_ : kb_;
        const float* bm = isq ? qm : km;
        const float* bv = isq ? qv : kv_;
        __nv_bfloat16* hi = isq ? hiq : hikv;
        __nv_bfloat16* lo = isq ? loq : lokv;
        int c0 = blockIdx.y * 64;
        int p0 = blockIdx.x * 32;
        int p = p0 + tx;
        int oy = p / OW, ox = p % OW;
        int iy0 = oy * stride - 1, ix0 = ox * stride - 1;
#pragma unroll
        for (int r = 0; r < 8; r++) {
            int c = c0 + ty + r * 8;
            float val = 0.f;
            if (p < P) {
                const float* xb = x + ((size_t)(b * CIN + c)) * (H * W);
                const float* wc = w + c * 9;
                float acc = 0.f;
#pragma unroll
                for (int dy = 0; dy < 3; dy++) {
                    int iy = iy0 + dy;
                    if (iy < 0 || iy >= H) continue;
#pragma unroll
                    for (int dx = 0; dx < 3; dx++) {
                        int ix = ix0 + dx;
                        if (ix < 0 || ix >= W) continue;
                        acc += xb[iy * W + ix] * wc[dy * 3 + dx];
                    }
                }
                float inv = bg[c] * rsqrtf(bv[c] + 1e-5f);
                val = (acc - bm[c]) * inv + bbp[c];
            }
            t[ty + r * 8][tx] = val;
        }
        __syncthreads();
#pragma unroll
        for (int r = 0; r < 4; r++) {
            int nl = ty + r * 8;
            int pp = p0 + nl;
            if (pp < P) {
                size_t n = (size_t)b * P + pp;
                uint32_t hv, lv;
                split2(t[2 * tx][nl], t[2 * tx + 1][nl], hv, lv);
                *(uint32_t*)(hi + n * CIN + c0 + 2 * tx) = hv;
                *(uint32_t*)(lo + n * CIN + c0 + 2 * tx) = lv;
            }
        }
    } else {
        // x transpose + split: b = z-128, c0 = y*32, p0 = x*32
        int b = z - 128;
        int p0 = blockIdx.x * 32, c0 = blockIdx.y * 32;
#pragma unroll
        for (int r = 0; r < 4; r++) {
            int c = c0 + ty + r * 8;
            int p = p0 + tx;
            t[ty + r * 8][tx] = (p < P1) ? x[((size_t)b * CIN + c) * P1 + p] : 0.f;
        }
        __syncthreads();
#pragma unroll
        for (int r = 0; r < 4; r++) {
            int p = p0 + ty + r * 8;
            int c = c0 + tx;
            if (p < P1) {
                float v = t[tx][ty + r * 8];
                __nv_bfloat16 h = __float2bfloat16(v);
                size_t o = ((size_t)b * P1 + p) * CIN + c;
                hix[o] = h;
                lox[o] = __float2bfloat16(v - __bfloat162float(h));
            }
        }
    }
}

// ---------------- merged 3-problem mma GEMM (K-chunk 32, 2 CTAs/SM) ----------------
#define GQ_CTAS  (4 * 392)    // 1568
#define GKV_CTAS (8 * 98)     // 784
#define GR_CTAS  392
__global__ void __launch_bounds__(256, 2)
mma_gemm_all(const __nv_bfloat16* __restrict__ hwq,  const __nv_bfloat16* __restrict__ lwq,
             const __nv_bfloat16* __restrict__ hiq,  const __nv_bfloat16* __restrict__ loq,
             float* __restrict__ Yq,
             const __nv_bfloat16* __restrict__ hwkv, const __nv_bfloat16* __restrict__ lwkv,
             const __nv_bfloat16* __restrict__ hikv, const __nv_bfloat16* __restrict__ lokv,
             float* __restrict__ Ykv,
             const __nv_bfloat16* __restrict__ hwds, const __nv_bfloat16* __restrict__ lwds,
             const __nv_bfloat16* __restrict__ hix,  const __nv_bfloat16* __restrict__ lox,
             float* __restrict__ Yr,
             const float* __restrict__ dg, const float* __restrict__ db,
             const float* __restrict__ dm, const float* __restrict__ dv) {
    extern __shared__ __nv_bfloat16 smem[];

    int bx = blockIdx.x;
    const __nv_bfloat16 *hiW, *loW, *hiX, *loX;
    float* Y;
    int CO, m0, n0;
    const float *bg = nullptr, *bb = nullptr, *bm = nullptr, *bv = nullptr;
    if (bx < GQ_CTAS) {
        hiW = hwq; loW = lwq; hiX = hiq; loX = loq; Y = Yq; CO = INNER;
        m0 = (bx & 3) * 128; n0 = (bx >> 2) * 128;
    } else if (bx < GQ_CTAS + GKV_CTAS) {
        int i = bx - GQ_CTAS;
        hiW = hwkv; loW = lwkv; hiX = hikv; loX = lokv; Y = Ykv; CO = 2 * INNER;
        m0 = (i & 7) * 128; n0 = (i >> 3) * 128;
    } else {
        int i = bx - GQ_CTAS - GKV_CTAS;
        hiW = hwds; loW = lwds; hiX = hix; loX = lox; Y = Yr; CO = DHEAD;
        m0 = 0; n0 = i * 128;
        bg = dg; bb = db; bm = dm; bv = dv;
    }

    int tid = threadIdx.x, lane = tid & 31, wid = tid >> 5;
    int warp_m = wid >> 2, warp_n = wid & 3;
    int lrow = tid >> 1, lhalf = tid & 1;

    float acc[4][4][4];
#pragma unroll
    for (int i = 0; i < 4; i++)
#pragma unroll
        for (int j = 0; j < 4; j++)
#pragma unroll
            for (int k = 0; k < 4; k++) acc[i][j][k] = 0.f;

    int a_row = warp_m * 64 + ((lane & 7) | (((lane >> 3) & 1) << 3));
    int a_off = a_row * (RSTRIDE * 2) + (lane >> 4) * 16;
    int b_row = warp_n * 32 + (lane & 7);
    int b_off = b_row * (RSTRIDE * 2) + ((lane >> 3) & 1) * 16;

#define LOADC(ch, buf) do { \
        int _kk = (ch) * KC; \
        const __nv_bfloat16* _p0 = hiW + (size_t)(m0 + lrow) * CIN + _kk + lhalf * 16; \
        const __nv_bfloat16* _p1 = loW + (size_t)(m0 + lrow) * CIN + _kk + lhalf * 16; \
        const __nv_bfloat16* _p2 = hiX + (size_t)(n0 + lrow) * CIN + _kk + lhalf * 16; \
        const __nv_bfloat16* _p3 = loX + (size_t)(n0 + lrow) * CIN + _kk + lhalf * 16; \
        uint32_t _b = smem_u32(smem) + (uint32_t)(buf) * (uint32_t)STAGE_B + lrow * 80u + lhalf * 32u; \
        CP_ASYNC16(_b + 0u * TILE_B,      _p0);      CP_ASYNC16(_b + 0u * TILE_B + 16, _p0 + 8); \
        CP_ASYNC16(_b + 1u * TILE_B,      _p1);      CP_ASYNC16(_b + 1u * TILE_B + 16, _p1 + 8); \
        CP_ASYNC16(_b + 2u * TILE_B,      _p2);      CP_ASYNC16(_b + 2u * TILE_B + 16, _p2 + 8); \
        CP_ASYNC16(_b + 3u * TILE_B,      _p3);      CP_ASYNC16(_b + 3u * TILE_B + 16, _p3 + 8); \
        CP_COMMIT(); \
    } while (0)

    LOADC(0, 0);

    for (int s = 0; s < NCHUNK; s++) {
        int buf = s & 1;
        if (s + 1 < NCHUNK) {
            LOADC(s + 1, buf ^ 1);
            CP_WAIT(1);
        } else {
            CP_WAIT(0);
        }
        __syncthreads();

        uint32_t base = smem_u32(smem) + (uint32_t)buf * (uint32_t)STAGE_B;
        uint32_t hiAo = base + a_off;
        uint32_t loAo = base + TILE_B + a_off;
        uint32_t hiBo = base + 2u * TILE_B + b_off;
        uint32_t loBo = base + 3u * TILE_B + b_off;
#pragma unroll
        for (int ks = 0; ks < 2; ks++) {
            uint32_t ah[4][4], al[4][4], bh2[4][2], bl2[4][2];
#pragma unroll
            for (int mt = 0; mt < 4; mt++) {
                uint32_t off = mt * 16 * (RSTRIDE * 2) + ks * 32;
                LDMX4(ah[mt], hiAo + off);
                LDMX4(al[mt], loAo + off);
            }
#pragma unroll
            for (int nt = 0; nt < 4; nt++) {
                uint32_t off = nt * 8 * (RSTRIDE * 2) + ks * 32;
                LDMX2(bh2[nt], hiBo + off);
                LDMX2(bl2[nt], loBo + off);
            }
#pragma unroll
            for (int mt = 0; mt < 4; mt++)
#pragma unroll
                for (int nt = 0; nt < 4; nt++) {
                    MMA_BF16(acc[mt][nt], ah[mt], bh2[nt]);
                    MMA_BF16(acc[mt][nt], al[mt], bh2[nt]);
                    MMA_BF16(acc[mt][nt], ah[mt], bl2[nt]);
                }
        }
        __syncthreads();
    }

    // smem-staged coalesced epilogue
    float* st = (float*)smem;     // 128 x 132 floats = 67584 B < 81920
    int g = lane >> 2, t4 = lane & 3;
#pragma unroll
    for (int mt = 0; mt < 4; mt++) {
        int mAl = warp_m * 64 + mt * 16 + g;
        int mBl = mAl + 8;
        int mA = m0 + mAl, mB = m0 + mBl;
        float sA = 1.f, hA = 0.f, sB = 1.f, hB = 0.f;
        if (bg) {
            if (mA < CO) { float iv = bg[mA] * rsqrtf(bv[mA] + 1e-5f); sA = iv; hA = bb[mA] - bm[mA] * iv; }
            if (mB < CO) { float iv = bg[mB] * rsqrtf(bv[mB] + 1e-5f); sB = iv; hB = bb[mB] - bm[mB] * iv; }
        }
#pragma unroll
        for (int nt = 0; nt < 4; nt++) {
            int nl = warp_n * 32 + nt * 8 + 2 * t4;
            st[nl * 132 + mAl]       = acc[mt][nt][0] * sA + hA;
            st[(nl + 1) * 132 + mAl] = acc[mt][nt][1] * sA + hA;
            st[nl * 132 + mBl]       = acc[mt][nt][2] * sB + hB;
            st[(nl + 1) * 132 + mBl] = acc[mt][nt][3] * sB + hB;
        }
    }
    __syncthreads();
    int row = tid >> 1, half = tid & 1;
    int cmax = CO - m0; if (cmax > 128) cmax = 128;
    int cstart = half * (cmax >> 1), cend = cstart + (cmax >> 1);
    float* dst = Y + (size_t)(n0 + row) * CO + m0;
    for (int col = cstart; col < cend; col += 4)
        *(float4*)(dst + col) = *(float4*)(st + row * 132 + col);
#undef LOADC
}

// ---------------- tensor-core attention + residual + LN + mean-pool ----------------
// one CTA per (b,h); 8 warps; each warp processes 16-query strips.
// smem: KHI[200][72], KLO[200][72], VT[64][216], QS per warp (hi+lo 16x72), SR[8][64]
#define KROWS   200
#define KSTR    72
#define VSTR    216
#define QS_ELE  (16 * KSTR)           // per warp per half
#define SM_KHI  0
#define SM_KLO  (KROWS * KSTR)
#define SM_VT   (2 * KROWS * KSTR)
#define SM_QS   (SM_VT + 64 * VSTR)
#define SM_BF16_TOT (SM_QS + 8 * 2 * QS_ELE)
#define ATTN_SMEM_B (SM_BF16_TOT * 2 + 8 * 64 * 4)

__global__ void __launch_bounds__(256, 1)
attn_mma_kernel(const float* __restrict__ qbuf,   // [n][512]
                const float* __restrict__ kvbuf,  // [n2][1024]
                const float* __restrict__ resb,   // [n][64]
                const float* __restrict__ lng, const float* __restrict__ lnb,
                float* __restrict__ out) {
    extern __shared__ __nv_bfloat16 sb[];
    __nv_bfloat16* KHI = sb + SM_KHI;
    __nv_bfloat16* KLO = sb + SM_KLO;
    __nv_bfloat16* VT  = sb + SM_VT;
    __nv_bfloat16* QSB = sb + SM_QS;
    float* SR = (float*)(sb + SM_BF16_TOT);   // [8][64]

    int bh = blockIdx.x;
    int b = bh >> 3, h = bh & 7;
    int tid = threadIdx.x, lane = tid & 31, wid = tid >> 5;
    int g = lane >> 2, t4 = lane & 3;

    // ---- load K hi/lo (rows 196..199 zeroed) ----
    const float* kvbase = kvbuf + (size_t)b * P2 * 1024 + h * 64;
    {
        int r = tid >> 1, hf = tid & 1;
#pragma unroll
        for (int j0 = 0; j0 < KROWS; j0 += 128) {
            int j = j0 + r;
            if (j < KROWS) {
                __nv_bfloat16* kh = KHI + j * KSTR + hf * 32;
                __nv_bfloat16* kl = KLO + j * KSTR + hf * 32;
                if (j < P2) {
                    const float4* src = (const float4*)(kvbase + (size_t)j * 1024 + hf * 32);
#pragma unroll
                    for (int k = 0; k < 8; k++) {
                        float4 v = src[k];
                        uint32_t h0, l0, h1, l1;
                        split2(v.x, v.y, h0, l0);
                        split2(v.z, v.w, h1, l1);
                        *(uint32_t*)(kh + k * 4)     = h0;
                        *(uint32_t*)(kh + k * 4 + 2) = h1;
                        *(uint32_t*)(kl + k * 4)     = l0;
                        *(uint32_t*)(kl + k * 4 + 2) = l1;
                    }
                } else {
#pragma unroll
                    for (int k = 0; k < 16; k++) {
                        *(uint32_t*)(kh + k * 2) = 0u;
                        *(uint32_t*)(kl + k * 2) = 0u;
                    }
                }
            }
        }
    }
    // ---- load V transposed (hi only); cols 196..207 zeroed ----
    {
        if (tid < P2) {
            const float* vsrc = kvbase + (size_t)tid * 1024 + 512;
#pragma unroll
            for (int d = 0; d < 64; d++)
                VT[d * VSTR + tid] = __float2bfloat16(vsrc[d]);
        } else if (tid < 208) {
#pragma unroll
            for (int d = 0; d < 64; d++)
                VT[d * VSTR + tid] = __float2bfloat16(0.f);
        }
    }
    __syncthreads();

    __nv_bfloat16* qhi = QSB + wid * 2 * QS_ELE;
    __nv_bfloat16* qlo = qhi + QS_ELE;
    uint32_t khiA = smem_u32(KHI), kloA = smem_u32(KLO), vtA = smem_u32(VT);
    uint32_t qhiA = smem_u32(qhi), qloA = smem_u32(qlo);

    uint32_t a_off = (((lane & 7) | (((lane >> 3) & 1) << 3)) * KSTR * 2) + (lane >> 4) * 16;
    uint32_t b_off = ((lane & 7) * KSTR * 2) + ((lane >> 3) & 1) * 16;
    uint32_t v_off = ((lane & 7) * VSTR * 2) + ((lane >> 3) & 1) * 16;

    float zacc[8][2];
#pragma unroll
    for (int i = 0; i < 8; i++) { zacc[i][0] = 0.f; zacc[i][1] = 0.f; }

    const size_t nb = (size_t)b * P1;

    for (int s = wid; s < 49; s += 8) {
        int i0 = s * 16;
        __syncwarp();
        // ---- stage Q strip (16 rows) hi/lo ----
        {
            int r = lane >> 1, hf = lane & 1;
            const float4* src = (const float4*)(qbuf + (nb + i0 + r) * INNER + h * 64 + hf * 32);
            __nv_bfloat16* qh = qhi + r * KSTR + hf * 32;
            __nv_bfloat16* ql = qlo + r * KSTR + hf * 32;
#pragma unroll
            for (int k = 0; k < 8; k++) {
                float4 v = src[k];
                uint32_t h0, l0, h1, l1;
                split2(v.x, v.y, h0, l0);
                split2(v.z, v.w, h1, l1);
                *(uint32_t*)(qh + k * 4)     = h0;
                *(uint32_t*)(qh + k * 4 + 2) = h1;
                *(uint32_t*)(ql + k * 4)     = l0;
                *(uint32_t*)(ql + k * 4 + 2) = l1;
            }
        }
        __syncwarp();

        // ---- A fragments for Q (4 k-blocks of 16) ----
        uint32_t ah[4][4], al[4][4];
#pragma unroll
        for (int kb = 0; kb < 4; kb++) {
            LDMX4(ah[kb], qhiA + a_off + kb * 32);
            LDMX4(al[kb], qloA + a_off + kb * 32);
        }

        // ---- QK^T: S[16][200] in 25 n-tiles ----
        float e[25][4];
#pragma unroll
        for (int nt = 0; nt < 25; nt++) {
            float c[4] = {0.f, 0.f, 0.f, 0.f};
            uint32_t roff = nt * 8 * (KSTR * 2);
#pragma unroll
            for (int kb = 0; kb < 4; kb++) {
                uint32_t bhf[2], blf[2];
                LDMX2(bhf, khiA + roff + b_off + kb * 32);
                LDMX2(blf, kloA + roff + b_off + kb * 32);
                MMA_BF16(c, ah[kb], bhf);
                MMA_BF16(c, al[kb], bhf);
                MMA_BF16(c, ah[kb], blf);
            }
            e[nt][0] = c[0]; e[nt][1] = c[1]; e[nt][2] = c[2]; e[nt][3] = c[3];
        }

        // ---- softmax (rows g and g+8) ----
#pragma unroll
        for (int nt = 0; nt < 25; nt++)
#pragma unroll
            for (int k = 0; k < 4; k++) e[nt][k] *= 0.125f;
        if (t4 >= 2) { e[24][0] = -1e30f; e[24][1] = -1e30f; e[24][2] = -1e30f; e[24][3] = -1e30f; }
        float mx0 = -1e30f, mx1 = -1e30f;
#pragma unroll
        for (int nt = 0; nt < 25; nt++) {
            mx0 = fmaxf(mx0, fmaxf(e[nt][0], e[nt][1]));
            mx1 = fmaxf(mx1, fmaxf(e[nt][2], e[nt][3]));
        }
        mx0 = fmaxf(mx0, __shfl_xor_sync(0xffffffffu, mx0, 1));
        mx0 = fmaxf(mx0, __shfl_xor_sync(0xffffffffu, mx0, 2));
        mx1 = fmaxf(mx1, __shfl_xor_sync(0xffffffffu, mx1, 1));
        mx1 = fmaxf(mx1, __shfl_xor_sync(0xffffffffu, mx1, 2));
        float sm0 = 0.f, sm1 = 0.f;
#pragma unroll
        for (int nt = 0; nt < 25; nt++) {
            e[nt][0] = __expf(e[nt][0] - mx0);
            e[nt][1] = __expf(e[nt][1] - mx0);
            e[nt][2] = __expf(e[nt][2] - mx1);
            e[nt][3] = __expf(e[nt][3] - mx1);
            sm0 += e[nt][0] + e[nt][1];
            sm1 += e[nt][2] + e[nt][3];
        }
        sm0 += __shfl_xor_sync(0xffffffffu, sm0, 1);
        sm0 += __shfl_xor_sync(0xffffffffu, sm0, 2);
        sm1 += __shfl_xor_sync(0xffffffffu, sm1, 1);
        sm1 += __shfl_xor_sync(0xffffffffu, sm1, 2);
        float inv0 = 1.f / sm0, inv1 = 1.f / sm1;

        // ---- P @ V : 13 k-blocks x 8 d-tiles, P split hi/lo ----
        float co[8][4];
#pragma unroll
        for (int i = 0; i < 8; i++) { co[i][0] = 0.f; co[i][1] = 0.f; co[i][2] = 0.f; co[i][3] = 0.f; }
#pragma unroll
        for (int kb2 = 0; kb2 < 13; kb2++) {
            int tA = 2 * kb2, tB = 2 * kb2 + 1;
            uint32_t p[4], pl[4];
            split2(e[tA][0], e[tA][1], p[0], pl[0]);
            split2(e[tA][2], e[tA][3], p[1], pl[1]);
            if (tB < 25) {
                split2(e[tB][0], e[tB][1], p[2], pl[2]);
                split2(e[tB][2], e[tB][3], p[3], pl[3]);
            } else {
                p[2] = 0u; p[3] = 0u; pl[2] = 0u; pl[3] = 0u;
            }
#pragma unroll
            for (int ntv = 0; ntv < 8; ntv++) {
                uint32_t bv2[2];
                LDMX2(bv2, vtA + ntv * 8 * (VSTR * 2) + v_off + kb2 * 32);
                MMA_BF16(co[ntv], p,  bv2);
                MMA_BF16(co[ntv], pl, bv2);
            }
        }

        // ---- normalize + residual + per-row LN stats ----
        int row0 = i0 + g, row1 = row0 + 8;
        const float* r0p = resb + (nb + row0) * 64;
        const float* r1p = resb + (nb + row1) * 64;
        float s10 = 0.f, s20 = 0.f, s11 = 0.f, s21 = 0.f;
#pragma unroll
        for (int ntv = 0; ntv < 8; ntv++) {
            int d = ntv * 8 + 2 * t4;
            float2 rv0 = *(const float2*)(r0p + d);
            float2 rv1 = *(const float2*)(r1p + d);
            float a0 = co[ntv][0] * inv0 + rv0.x;
            float a1 = co[ntv][1] * inv0 + rv0.y;
            float b0 = co[ntv][2] * inv1 + rv1.x;
            float b1 = co[ntv][3] * inv1 + rv1.y;
            co[ntv][0] = a0; co[ntv][1] = a1; co[ntv][2] = b0; co[ntv][3] = b1;
            s10 += a0 + a1; s20 += a0 * a0 + a1 * a1;
            s11 += b0 + b1; s21 += b0 * b0 + b1 * b1;
        }
        s10 += __shfl_xor_sync(0xffffffffu, s10, 1);
        s10 += __shfl_xor_sync(0xffffffffu, s10, 2);
        s20 += __shfl_xor_sync(0xffffffffu, s20, 1);
        s20 += __shfl_xor_sync(0xffffffffu, s20, 2);
        s11 += __shfl_xor_sync(0xffffffffu, s11, 1);
        s11 += __shfl_xor_sync(0xffffffffu, s11, 2);
        s21 += __shfl_xor_sync(0xffffffffu, s21, 1);
        s21 += __shfl_xor_sync(0xffffffffu, s21, 2);
        float mean0 = s10 * (1.f / 64.f);
        float var0  = fmaxf(s20 * (1.f / 64.f) - mean0 * mean0, 0.f);
        float istd0 = 1.f / (sqrtf(var0) + 1e-5f);
        float mean1 = s11 * (1.f / 64.f);
        float var1  = fmaxf(s21 * (1.f / 64.f) - mean1 * mean1, 0.f);
        float istd1 = 1.f / (sqrtf(var1) + 1e-5f);
#pragma unroll
        for (int ntv = 0; ntv < 8; ntv++) {
            zacc[ntv][0] += (co[ntv][0] - mean0) * istd0 + (co[ntv][2] - mean1) * istd1;
            zacc[ntv][1] += (co[ntv][1] - mean0) * istd0 + (co[ntv][3] - mean1) * istd1;
        }
    }

    // ---- reduce zacc across g (lanes differing in bits 2..4), then across warps ----
#pragma unroll
    for (int ntv = 0; ntv < 8; ntv++) {
#pragma unroll
        for (int off = 4; off <= 16; off <<= 1) {
            zacc[ntv][0] += __shfl_xor_sync(0xffffffffu, zacc[ntv][0], off);
            zacc[ntv][1] += __shfl_xor_sync(0xffffffffu, zacc[ntv][1], off);
        }
    }
    if (g == 0) {
#pragma unroll
        for (int ntv = 0; ntv < 8; ntv++) {
            SR[wid * 64 + ntv * 8 + 2 * t4]     = zacc[ntv][0];
            SR[wid * 64 + ntv * 8 + 2 * t4 + 1] = zacc[ntv][1];
        }
    }
    __syncthreads();
    if (tid < 64) {
        float sum = 0.f;
#pragma unroll
        for (int w = 0; w < 8; w++) sum += SR[w * 64 + tid];
        out[(size_t)bh * 64 + tid] = sum * (1.f / 784.f) * lng[h * 64 + tid] + lnb[h * 64 + tid];
    }
}

// ---------------- launch ----------------
extern "C" void kernel_launch(void* const* d_in, const int* in_sizes, int n_in,
                              void* d_out, int out_size) {
    (void)in_sizes; (void)n_in; (void)out_size;
    const float* x      = (const float*)d_in[0];
    const float* w_dwq  = (const float*)d_in[1];
    const float* w_pwq  = (const float*)d_in[2];
    const float* w_dwkv = (const float*)d_in[3];
    const float* w_pwkv = (const float*)d_in[4];
    const float* w_ds   = (const float*)d_in[5];
    const float* ln_g   = (const float*)d_in[6];
    const float* ln_b   = (const float*)d_in[7];
    const float* bnq_g  = (const float*)d_in[8];
    const float* bnq_b  = (const float*)d_in[9];
    const float* bnq_m  = (const float*)d_in[10];
    const float* bnq_v  = (const float*)d_in[11];
    const float* bnkv_g = (const float*)d_in[12];
    const float* bnkv_b = (const float*)d_in[13];
    const float* bnkv_m = (const float*)d_in[14];
    const float* bnkv_v = (const float*)d_in[15];
    const float* bnds_g = (const float*)d_in[16];
    const float* bnds_b = (const float*)d_in[17];
    const float* bnds_m = (const float*)d_in[18];
    const float* bnds_v = (const float*)d_in[19];
    float* out = (float*)d_out;

    float *qbuf, *kvbuf, *resb;
    __nv_bfloat16 *hiq, *loq, *hikv, *lokv, *hix, *lox;
    __nv_bfloat16 *hwq, *lwq, *hwkv, *lwkv, *hwds, *lwds;
    cudaGetSymbolAddress((void**)&hiq,  g_hiq);
    cudaGetSymbolAddress((void**)&loq,  g_loq);
    cudaGetSymbolAddress((void**)&hikv, g_hikv);
    cudaGetSymbolAddress((void**)&lokv, g_lokv);
    cudaGetSymbolAddress((void**)&hix,  g_hix);
    cudaGetSymbolAddress((void**)&lox,  g_lox);
    cudaGetSymbolAddress((void**)&hwq,  g_hwq);
    cudaGetSymbolAddress((void**)&lwq,  g_lwq);
    cudaGetSymbolAddress((void**)&hwkv, g_hwkv);
    cudaGetSymbolAddress((void**)&lwkv, g_lwkv);
    cudaGetSymbolAddress((void**)&hwds, g_hwds);
    cudaGetSymbolAddress((void**)&lwds, g_lwds);
    cudaGetSymbolAddress((void**)&qbuf, g_q);
    cudaGetSymbolAddress((void**)&kvbuf, g_kv);
    cudaGetSymbolAddress((void**)&resb, g_res);

    // #1: weight splits
    {
        int tot = WQ_N + WKV_N + WDS_N;
        wsplit_all_kernel<<<(tot + 255) / 256, 256>>>(w_pwq, w_pwkv, w_ds,
                                                      hwq, lwq, hwkv, lwkv, hwds, lwds);
    }
    // #2: merged prep (dwconv-q, dwconv-kv, x transpose; all + split)
    {
        dim3 grid(25, 20, 192);
        prep_kernel<<<grid, dim3(32, 8)>>>(x,
                                           w_dwq, bnq_g, bnq_b, bnq_m, bnq_v,
                                           w_dwkv, bnkv_g, bnkv_b, bnkv_m, bnkv_v,
                                           hiq, loq, hikv, lokv, hix, lox);
    }
    // #3: merged GEMMs (q + kv + residual)
    {
        size_t gemm_smem = 2 * STAGE_B;   // 81920
        cudaFuncSetAttribute(mma_gemm_all, cudaFuncAttributeMaxDynamicSharedMemorySize, (int)gemm_smem);
        mma_gemm_all<<<GQ_CTAS + GKV_CTAS + GR_CTAS, 256, gemm_smem>>>(
            hwq, lwq, hiq, loq, qbuf,
            hwkv, lwkv, hikv, lokv, kvbuf,
            hwds, lwds, hix, lox, resb,
            bnds_g, bnds_b, bnds_m, bnds_v);
    }
    // #4: tensor-core attention (profiled launch)
    {
        cudaFuncSetAttribute(attn_mma_kernel, cudaFuncAttributeMaxDynamicSharedMemorySize, ATTN_SMEM_B);
        attn_mma_kernel<<<BATCH * NHEAD, 256, ATTN_SMEM_B>>>(qbuf, kvbuf, resb, ln_g, ln_b, out);
    }
}